// round 13
// baseline (speedup 1.0000x reference)
#include <cuda_runtime.h>
#include <cuda_bf16.h>
#include <cstdint>

// ---------------- problem constants ----------------
#define SQ   256
#define BB   8
#define VV   32000
#define EE   300
#define HH   512
#define ERD  64
#define XDIM (EE + ERD)     // 364
#define XH   (XDIM + HH)    // 876
#define MM   (SQ * BB)      // 2048

#define LSTM_BLOCKS 64
#define HPB 8               // h indices per block
#define NI  55              // k-slices per thread: k = 16*i + c, KPAD=880

#define CAND_MAX 64
#define CAND_EPS 5e-4f

// xh smem layout: (k>>4)*128 + (b>>2)*64 + (k&15)*4 + (b&3)
#define XH2_FLOATS (NI * 128)        // 7040 floats per buffer
#define XG 23                        // k-groups covering x part (k < 368)
#define XSEQ2_FLOATS (XG * 128)      // 2944 floats per step
__device__ __forceinline__ int xh_off(int k, int b) {
    return (k >> 4) * 128 + (b >> 2) * 64 + (k & 15) * 4 + (b & 3);
}

// ---------------- scratch ----------------
__device__ float g_xseq2[SQ * XSEQ2_FLOATS];   // x in xh layout, per step (~3MB)
__device__ float g_hs[MM * HH];                // [s*8+b][H] for logits/rescore
__device__ float g_hs2[SQ * HH * BB];          // [s][j][b] staging layout (4MB)
__device__ float g_logits[(size_t)MM * VV];
__device__ unsigned long long g_best[MM];
__device__ float g_Z[MM];
__device__ int   g_candv[MM * CAND_MAX];
__device__ int   g_candn[MM];
__device__ int   g_vstar[MM];
__device__ unsigned g_bars[SQ];

// ---------------- helpers ----------------
__device__ __forceinline__ void ffma2(unsigned long long &d, unsigned long long a,
                                      unsigned long long b) {
    asm("fma.rn.f32x2 %0, %1, %2, %0;" : "+l"(d) : "l"(a), "l"(b));
}
__device__ __forceinline__ unsigned long long dup2(float f) {
    unsigned long long d;
    asm("mov.b64 %0, {%1, %1};" : "=l"(d) : "f"(f));
    return d;
}
__device__ __forceinline__ float2 unpack2(unsigned long long a) {
    float2 f;
    asm("mov.b64 {%0, %1}, %2;" : "=f"(f.x), "=f"(f.y) : "l"(a));
    return f;
}
__device__ __forceinline__ unsigned long long make_key(float logit, int v) {
    unsigned u = __float_as_uint(logit);
    u = (u & 0x80000000u) ? ~u : (u | 0x80000000u);
    return ((unsigned long long)u << 32) | (unsigned)(0xFFFFFFFFu - (unsigned)v);
}
__device__ __forceinline__ float key_to_float(unsigned long long key) {
    unsigned u = (unsigned)(key >> 32);
    unsigned fb = (u & 0x80000000u) ? (u ^ 0x80000000u) : ~u;
    return __uint_as_float(fb);
}

// ---------------- kernel 0: zero state ----------------
__global__ void k_zero() {
    int t = blockIdx.x * blockDim.x + threadIdx.x;
    if (t < MM) { g_best[t] = 0ull; g_candn[t] = 0; }
    if (t < SQ) g_bars[t] = 0u;
}

// ---------------- kernel 1: x_seq (written directly in xh layout) ------------
__global__ void k_xseq(const int* __restrict__ tokens, const int* __restrict__ relations,
                       const float* __restrict__ embed, const float* __restrict__ rel_emb) {
    int sb = blockIdx.x;
    int s = sb >> 3, b = sb & 7;
    int k = threadIdx.x;
    if (k >= XDIM) return;
    float val;
    if (k < ERD) {
        int r = relations[s * BB + b];
        val = rel_emb[r * ERD + k];
    } else {
        int tok = (s == 0) ? 0 : tokens[(s - 1) * BB + b];
        val = embed[tok * EE + (k - ERD)];
    }
    g_xseq2[s * XSEQ2_FLOATS + xh_off(k, b)] = val;
}

// ---------------- kernel 2: persistent LSTM v4 ----------------
// 64 blocks x 256 threads, 8 h/block -> 32 gate rows; thread (r, c) handles
// rows r, r+16 over k = 16i+c. Staging now fully coalesced:
//  - x: g_xseq2 already in xh layout -> float4 copies
//  - h: g_hs2[s][j][b] -> float4 {h[j][b0..3]} loads, STS.128 into xh layout
__global__ __launch_bounds__(256, 1) void k_lstm(
    const float* __restrict__ hiddens,
    const float* __restrict__ W_ih, const float* __restrict__ W_hh,
    const float* __restrict__ b_ih, const float* __restrict__ b_hh) {
    extern __shared__ float sm[];
    float* xhA    = sm;                        // 7040
    float* xhB    = xhA + XH2_FLOATS;          // 7040
    float* gate_s = xhB + XH2_FLOATS;          // 256
    float* c_s    = gate_s + 256;              // 64
    float* bias_s = c_s + 64;                  // 32
    double* nl_s  = (double*)(bias_s + 32);    // 256 doubles

    const int tid = threadIdx.x;
    const int r = tid >> 4;
    const int c = tid & 15;
    const int j0 = blockIdx.x * HPB;

    float wA[NI], wB[NI];
    {
        const int rA = r, rB = r + 16;
        const int growA = (rA >> 3) * HH + j0 + (rA & 7);
        const int growB = (rB >> 3) * HH + j0 + (rB & 7);
        #pragma unroll
        for (int i = 0; i < NI; ++i) {
            int k = 16 * i + c;
            wA[i] = (k < XDIM) ? W_ih[growA * XDIM + k]
                  : (k < XH)   ? W_hh[growA * HH + (k - XDIM)] : 0.0f;
            wB[i] = (k < XDIM) ? W_ih[growB * XDIM + k]
                  : (k < XH)   ? W_hh[growB * HH + (k - XDIM)] : 0.0f;
        }
    }
    if (tid < 32) {
        int g2 = tid >> 3, j2 = tid & 7;
        bias_s[tid] = b_ih[g2 * HH + j0 + j2] + b_hh[g2 * HH + j0 + j2];
    }
    if (tid < 64) {
        int j2 = tid >> 3, b = tid & 7;
        c_s[tid] = hiddens[b * HH + j0 + j2];
    }
    if (tid < 64) {   // zero pad k=876..879 in both buffers
        int buf = tid >> 5, kk = 876 + ((tid >> 3) & 3), b = tid & 7;
        (buf ? xhB : xhA)[xh_off(kk, b)] = 0.0f;
    }
    // stage x_0 (direct layout copy)
    for (int idx = tid; idx < XSEQ2_FLOATS / 4; idx += 256)
        *((float4*)xhA + idx) = *((const float4*)g_xseq2 + idx);
    __syncthreads();

    float* cur = xhA;
    float* nxt = xhB;
    const unsigned long long ONE2 = dup2(1.0f);

    for (int s = 0; s < SQ; ++s) {
        // stage h_{s-1}: 1024 float4s, thread handles (j = idx&511, half = idx>>9)
        if (s == 0) {
            #pragma unroll
            for (int it = 0; it < 4; ++it) {
                int idx = tid + it * 256;
                int j = idx & 511, half = idx >> 9;
                float4 v;
                v.x = hiddens[(half * 4 + 0) * HH + j];
                v.y = hiddens[(half * 4 + 1) * HH + j];
                v.z = hiddens[(half * 4 + 2) * HH + j];
                v.w = hiddens[(half * 4 + 3) * HH + j];
                int k = XDIM + j;
                *(float4*)(cur + (k >> 4) * 128 + half * 64 + (k & 15) * 4) = v;
            }
        } else {
            const float4* src = (const float4*)(g_hs2 + (size_t)(s - 1) * HH * BB);
            #pragma unroll
            for (int it = 0; it < 4; ++it) {
                int idx = tid + it * 256;
                int j = idx >> 1, half = idx & 1;
                float4 v = __ldcg(src + idx);
                int k = XDIM + j;
                *(float4*)(cur + (k >> 4) * 128 + half * 64 + (k & 15) * 4) = v;
            }
        }
        __syncthreads();

        // gate partials
        unsigned long long a0 = 0, a1 = 0, a2 = 0, a3 = 0;
        unsigned long long a4 = 0, a5 = 0, a6 = 0, a7 = 0;
        const float* base = cur + c * 4;
        #pragma unroll
        for (int i = 0; i < NI; ++i) {
            ulonglong2 x01 = *(const ulonglong2*)(base + i * 128);       // b0..3
            ulonglong2 x23 = *(const ulonglong2*)(base + i * 128 + 64);  // b4..7
            unsigned long long wwA = dup2(wA[i]);
            unsigned long long wwB = dup2(wB[i]);
            ffma2(a0, x01.x, wwA); ffma2(a1, x01.y, wwA);
            ffma2(a2, x23.x, wwA); ffma2(a3, x23.y, wwA);
            ffma2(a4, x01.x, wwB); ffma2(a5, x01.y, wwB);
            ffma2(a6, x23.x, wwB); ffma2(a7, x23.y, wwB);
        }
        #pragma unroll
        for (int mask = 1; mask < 16; mask <<= 1) {
            ffma2(a0, __shfl_xor_sync(0xFFFFFFFFu, a0, mask), ONE2);
            ffma2(a1, __shfl_xor_sync(0xFFFFFFFFu, a1, mask), ONE2);
            ffma2(a2, __shfl_xor_sync(0xFFFFFFFFu, a2, mask), ONE2);
            ffma2(a3, __shfl_xor_sync(0xFFFFFFFFu, a3, mask), ONE2);
            ffma2(a4, __shfl_xor_sync(0xFFFFFFFFu, a4, mask), ONE2);
            ffma2(a5, __shfl_xor_sync(0xFFFFFFFFu, a5, mask), ONE2);
            ffma2(a6, __shfl_xor_sync(0xFFFFFFFFu, a6, mask), ONE2);
            ffma2(a7, __shfl_xor_sync(0xFFFFFFFFu, a7, mask), ONE2);
        }
        if (c == 0) {
            unsigned long long* gs = (unsigned long long*)gate_s;
            gs[r * 4 + 0] = a0; gs[r * 4 + 1] = a1;
            gs[r * 4 + 2] = a2; gs[r * 4 + 3] = a3;
            gs[(r + 16) * 4 + 0] = a4; gs[(r + 16) * 4 + 1] = a5;
            gs[(r + 16) * 4 + 2] = a6; gs[(r + 16) * 4 + 3] = a7;
        }
        __syncthreads();

        // cell phase A: one DP nonlinearity per thread
        {
            int grow = tid >> 3;
            double val = (double)(gate_s[tid] + bias_s[grow]);
            int gg = grow >> 3;
            nl_s[tid] = (gg == 2) ? tanh(val) : 1.0 / (1.0 + exp(-val));
        }
        __syncthreads();
        // cell phase B: 64 threads; write h to BOTH layouts
        if (tid < 64) {
            int j2 = tid >> 3, b = tid & 7;
            double si = nl_s[tid];
            double sf = nl_s[64 + tid];
            double tg = nl_s[128 + tid];
            double so = nl_s[192 + tid];
            double cn = sf * (double)c_s[tid] + si * tg;
            float cnf = (float)cn;
            float hnf = (float)(so * tanh((double)cnf));
            c_s[tid] = cnf;
            g_hs[(size_t)(s * 8 + b) * HH + j0 + j2] = hnf;
            g_hs2[(size_t)s * HH * BB + (j0 + j2) * 8 + b] = hnf;
        }
        __syncthreads();

        if (s + 1 < SQ) {
            // stage x_{s+1} (layout copy) — overlaps barrier spin
            const float4* xsrc = (const float4*)(g_xseq2 + (size_t)(s + 1) * XSEQ2_FLOATS);
            for (int idx = tid; idx < XSEQ2_FLOATS / 4; idx += 256)
                *((float4*)nxt + idx) = xsrc[idx];
            if (tid == 0) {
                asm volatile("red.release.gpu.global.add.u32 [%0], %1;"
                             :: "l"(&g_bars[s]), "r"(1u) : "memory");
                unsigned v;
                do {
                    asm volatile("ld.acquire.gpu.global.u32 %0, [%1];"
                                 : "=r"(v) : "l"(&g_bars[s]) : "memory");
                } while (v < (unsigned)LSTM_BLOCKS);
            }
            __syncthreads();
        }
        float* tmp = cur; cur = nxt; nxt = tmp;
    }
}

// ---------------- kernel 3: fp32 f32x2 logits GEMM (dup-A, 22-issue mix) -----
// A stored PRE-DUPLICATED as f32x2 pairs -> inner loop = 2 LDS.128 (a-dups) +
// 4 LDS.64 (w, 8B lane stride, conflict-free) + 16 FFMA2. Same operand order
// and sequential-k accumulation as R12 -> bit-identical logits.
#define BMX 64
#define BNX 128
#define BKX 16

__global__ __launch_bounds__(256, 2) void k_logits(const float* __restrict__ Wout,
                                                   const float* __restrict__ bout) {
    __shared__ unsigned long long sA[BKX * BMX];     // dup'd a, [k][m] (8KB)
    __shared__ float sW[BKX * BNX];                  // [k][n] (8KB)
    __shared__ unsigned long long sKey[BMX];

    const int tid = threadIdx.x;
    const int n0 = blockIdx.x * BNX;
    const int m0 = blockIdx.y * BMX;
    const int tm = tid >> 4;            // m = tm*4 + 0..3
    const int tn = tid & 15;            // n-pairs at tn*2 + j*32

    if (tid < BMX) sKey[tid] = 0ull;

    const int ar = tid >> 2;
    const int ak = (tid & 3) * 4;
    const int wr = tid >> 1;
    const int wk = (tid & 1) * 8;
    const float* gA = g_hs + (size_t)(m0 + ar) * HH + ak;
    const float* gW = Wout + (size_t)(n0 + wr) * HH + wk;

    unsigned long long acc[4][4];
    #pragma unroll
    for (int m = 0; m < 4; ++m)
        #pragma unroll
        for (int j = 0; j < 4; ++j) acc[m][j] = 0ull;

    float4 pa  = *(const float4*)gA;
    float4 pw0 = *(const float4*)gW;
    float4 pw1 = *(const float4*)(gW + 4);

    const int NT = HH / BKX;            // 32
    for (int t = 0; t < NT; ++t) {
        sA[(ak + 0) * BMX + ar] = dup2(pa.x);
        sA[(ak + 1) * BMX + ar] = dup2(pa.y);
        sA[(ak + 2) * BMX + ar] = dup2(pa.z);
        sA[(ak + 3) * BMX + ar] = dup2(pa.w);
        sW[(wk + 0) * BNX + wr] = pw0.x;
        sW[(wk + 1) * BNX + wr] = pw0.y;
        sW[(wk + 2) * BNX + wr] = pw0.z;
        sW[(wk + 3) * BNX + wr] = pw0.w;
        sW[(wk + 4) * BNX + wr] = pw1.x;
        sW[(wk + 5) * BNX + wr] = pw1.y;
        sW[(wk + 6) * BNX + wr] = pw1.z;
        sW[(wk + 7) * BNX + wr] = pw1.w;
        __syncthreads();
        if (t + 1 < NT) {
            pa  = *(const float4*)(gA + (t + 1) * BKX);
            pw0 = *(const float4*)(gW + (t + 1) * BKX);
            pw1 = *(const float4*)(gW + (t + 1) * BKX + 4);
        }
        #pragma unroll
        for (int k = 0; k < BKX; ++k) {
            ulonglong2 a01 = *(const ulonglong2*)(sA + k * BMX + tm * 4);
            ulonglong2 a23 = *(const ulonglong2*)(sA + k * BMX + tm * 4 + 2);
            const float* wrow = sW + k * BNX + tn * 2;
            unsigned long long w0 = *(const unsigned long long*)(wrow);
            unsigned long long w1 = *(const unsigned long long*)(wrow + 32);
            unsigned long long w2 = *(const unsigned long long*)(wrow + 64);
            unsigned long long w3 = *(const unsigned long long*)(wrow + 96);
            ffma2(acc[0][0], w0, a01.x); ffma2(acc[0][1], w1, a01.x);
            ffma2(acc[0][2], w2, a01.x); ffma2(acc[0][3], w3, a01.x);
            ffma2(acc[1][0], w0, a01.y); ffma2(acc[1][1], w1, a01.y);
            ffma2(acc[1][2], w2, a01.y); ffma2(acc[1][3], w3, a01.y);
            ffma2(acc[2][0], w0, a23.x); ffma2(acc[2][1], w1, a23.x);
            ffma2(acc[2][2], w2, a23.x); ffma2(acc[2][3], w3, a23.x);
            ffma2(acc[3][0], w0, a23.y); ffma2(acc[3][1], w1, a23.y);
            ffma2(acc[3][2], w2, a23.y); ffma2(acc[3][3], w3, a23.y);
        }
        __syncthreads();
    }

    // epilogue
    float bias[4][2];
    #pragma unroll
    for (int j = 0; j < 4; ++j) {
        bias[j][0] = __ldg(&bout[n0 + tn * 2 + j * 32]);
        bias[j][1] = __ldg(&bout[n0 + tn * 2 + j * 32 + 1]);
    }
    #pragma unroll
    for (int m = 0; m < 4; ++m) {
        int m_loc = tm * 4 + m;
        float* lrow = g_logits + (size_t)(m0 + m_loc) * VV + n0;
        unsigned long long best = 0ull;
        #pragma unroll
        for (int j = 0; j < 4; ++j) {
            float2 f = unpack2(acc[m][j]);
            float l0 = f.x + bias[j][0];
            float l1 = f.y + bias[j][1];
            int nn = tn * 2 + j * 32;
            *(float2*)(lrow + nn) = make_float2(l0, l1);
            unsigned long long k0 = make_key(l0, n0 + nn);
            unsigned long long k1 = make_key(l1, n0 + nn + 1);
            if (k0 > best) best = k0;
            if (k1 > best) best = k1;
        }
        atomicMax(&sKey[m_loc], best);
    }
    __syncthreads();
    if (tid < BMX) atomicMax(&g_best[m0 + tid], sKey[tid]);
}

// ---------------- kernel 3b: per-row Z + candidates ----------------
__global__ __launch_bounds__(256) void k_scan() {
    const int row = blockIdx.x;
    const int tid = threadIdx.x;
    __shared__ float sSum[256];
    __shared__ int sCnt;
    if (tid == 0) sCnt = 0;
    __syncthreads();

    const float rowmax = key_to_float(g_best[row]);
    const float th = rowmax - CAND_EPS;
    const float* lrow = g_logits + (size_t)row * VV;

    float acc = 0.0f;
    for (int v = tid; v < VV; v += 256) {
        float l = lrow[v];
        acc += expf(l - rowmax);
        if (l >= th) {
            int idx = atomicAdd(&sCnt, 1);
            if (idx < CAND_MAX) g_candv[row * CAND_MAX + idx] = v;
        }
    }
    sSum[tid] = acc;
    __syncthreads();
    for (int st = 128; st > 0; st >>= 1) {
        if (tid < st) sSum[tid] += sSum[tid + st];
        __syncthreads();
    }
    if (tid == 0) {
        g_Z[row] = sSum[0];
        g_candn[row] = (sCnt < CAND_MAX) ? sCnt : CAND_MAX;
    }
}

// ---------------- kernel 3c: fp64 rescore + quantized-softmax argmax ---------
__global__ __launch_bounds__(256) void k_rescore(const float* __restrict__ Wout,
                                                 const float* __restrict__ bout) {
    const int row = blockIdx.x;
    const int tid = threadIdx.x;
    const int warp = tid >> 5, lane = tid & 31;
    __shared__ double sL[CAND_MAX];

    const int n = g_candn[row];
    const float* hrow = g_hs + (size_t)row * HH;

    for (int ci = warp; ci < n; ci += 8) {
        int v = g_candv[row * CAND_MAX + ci];
        const float* wrow = Wout + (size_t)v * HH;
        double d = 0.0;
        #pragma unroll
        for (int k = lane; k < HH; k += 32)
            d += (double)hrow[k] * (double)wrow[k];
        #pragma unroll
        for (int off = 16; off > 0; off >>= 1)
            d += __shfl_down_sync(0xFFFFFFFFu, d, off);
        if (lane == 0) sL[ci] = d + (double)bout[v];
    }
    __syncthreads();

    if (tid == 0) {
        if (n <= 1) {
            g_vstar[row] = (n == 1) ? g_candv[row * CAND_MAX]
                                    : (int)(0xFFFFFFFFu - (unsigned)(g_best[row] & 0xFFFFFFFFull));
        } else {
            double M = sL[0];
            for (int i = 1; i < n; ++i) if (sL[i] > M) M = sL[i];
            float Z = g_Z[row];
            float bestp = -1.0f;
            int bestv = 0x7FFFFFFF;
            for (int i = 0; i < n; ++i) {
                float e = (float)exp(sL[i] - M);
                float p = __fdiv_rn(e, Z);
                int v = g_candv[row * CAND_MAX + i];
                if (p > bestp || (p == bestp && v < bestv)) { bestp = p; bestv = v; }
            }
            g_vstar[row] = bestv;
        }
    }
}

// ---------------- kernel 4: gather ----------------
__global__ void k_gather(const float* __restrict__ transfer, float* __restrict__ out) {
    int row = blockIdx.x;
    int vstar = g_vstar[row];
    const float* src = transfer + (size_t)vstar * EE;
    float* dst = out + (size_t)row * EE;
    for (int e = threadIdx.x; e < EE; e += blockDim.x) dst[e] = src[e];
}

// ---------------- launch ----------------
extern "C" void kernel_launch(void* const* d_in, const int* in_sizes, int n_in,
                              void* d_out, int out_size) {
    const int*   tokens    = (const int*)d_in[0];
    const int*   relations = (const int*)d_in[1];
    const float* hiddens   = (const float*)d_in[2];
    const float* embed     = (const float*)d_in[3];
    const float* transfer  = (const float*)d_in[4];
    const float* rel_emb   = (const float*)d_in[5];
    const float* W_ih      = (const float*)d_in[6];
    const float* W_hh      = (const float*)d_in[7];
    const float* b_ih      = (const float*)d_in[8];
    const float* b_hh      = (const float*)d_in[9];
    const float* W_out     = (const float*)d_in[10];
    const float* b_out     = (const float*)d_in[11];
    float* out = (float*)d_out;

    k_zero<<<8, 256>>>();
    k_xseq<<<MM, 384>>>(tokens, relations, embed, rel_emb);

    size_t smem = (size_t)(2 * XH2_FLOATS + 256 + 64 + 32) * sizeof(float)
                + 256 * sizeof(double);
    cudaFuncSetAttribute(k_lstm, cudaFuncAttributeMaxDynamicSharedMemorySize, (int)smem);
    k_lstm<<<LSTM_BLOCKS, 256, smem>>>(hiddens, W_ih, W_hh, b_ih, b_hh);

    k_logits<<<dim3(VV / BNX, MM / BMX), 256>>>(W_out, b_out);
    k_scan<<<MM, 256>>>();
    k_rescore<<<MM, 256>>>(W_out, b_out);
    k_gather<<<MM, 128>>>(transfer, out);
}

// round 14
// speedup vs baseline: 1.2132x; 1.2132x over previous
#include <cuda_runtime.h>
#include <cuda_bf16.h>
#include <cstdint>

// ---------------- problem constants ----------------
#define SQ   256
#define BB   8
#define VV   32000
#define EE   300
#define HH   512
#define ERD  64
#define XDIM (EE + ERD)     // 364
#define XH   (XDIM + HH)    // 876
#define MM   (SQ * BB)      // 2048

#define LSTM_BLOCKS 64
#define HPB 8               // h indices per block
#define NIH 32              // h k-slices per thread: k_h = 16*i + c

#define CAND_MAX 64
#define CAND_EPS 5e-4f

// h smem layout: (j>>4)*128 + (b>>2)*64 + (j&15)*4 + (b&3)
#define HS_FLOATS (NIH * 128)        // 4096

// ---------------- scratch ----------------
__device__ float g_xseq[MM * XDIM];            // x in [sb][k] layout
__device__ float g_xg[SQ * 4 * HH * BB];       // x-part gates [s][grow][b] (16.8MB)
__device__ float g_hs[MM * HH];                // [s*8+b][H] for logits/rescore
__device__ float g_hs2[SQ * HH * BB];          // [s][j][b] staging layout
__device__ float g_logits[(size_t)MM * VV];
__device__ unsigned long long g_best[MM];
__device__ float g_Z[MM];
__device__ int   g_candv[MM * CAND_MAX];
__device__ int   g_candn[MM];
__device__ int   g_vstar[MM];
__device__ unsigned g_bars[SQ];

// ---------------- helpers ----------------
__device__ __forceinline__ void ffma2(unsigned long long &d, unsigned long long a,
                                      unsigned long long b) {
    asm("fma.rn.f32x2 %0, %1, %2, %0;" : "+l"(d) : "l"(a), "l"(b));
}
__device__ __forceinline__ unsigned long long dup2(float f) {
    unsigned long long d;
    asm("mov.b64 %0, {%1, %1};" : "=l"(d) : "f"(f));
    return d;
}
__device__ __forceinline__ float2 unpack2(unsigned long long a) {
    float2 f;
    asm("mov.b64 {%0, %1}, %2;" : "=f"(f.x), "=f"(f.y) : "l"(a));
    return f;
}
__device__ __forceinline__ unsigned long long make_key(float logit, int v) {
    unsigned u = __float_as_uint(logit);
    u = (u & 0x80000000u) ? ~u : (u | 0x80000000u);
    return ((unsigned long long)u << 32) | (unsigned)(0xFFFFFFFFu - (unsigned)v);
}
__device__ __forceinline__ float key_to_float(unsigned long long key) {
    unsigned u = (unsigned)(key >> 32);
    unsigned fb = (u & 0x80000000u) ? (u ^ 0x80000000u) : ~u;
    return __uint_as_float(fb);
}

// ---------------- kernel 0: zero state ----------------
__global__ void k_zero() {
    int t = blockIdx.x * blockDim.x + threadIdx.x;
    if (t < MM) { g_best[t] = 0ull; g_candn[t] = 0; }
    if (t < SQ) g_bars[t] = 0u;
}

// ---------------- kernel 1: x_seq (plain [sb][k] layout) ---------------------
__global__ void k_xseq(const int* __restrict__ tokens, const int* __restrict__ relations,
                       const float* __restrict__ embed, const float* __restrict__ rel_emb) {
    int sb = blockIdx.x;
    int s = sb >> 3, b = sb & 7;
    int k = threadIdx.x;
    if (k >= XDIM) return;
    float val;
    if (k < ERD) {
        int r = relations[s * BB + b];
        val = rel_emb[r * ERD + k];
    } else {
        int tok = (s == 0) ? 0 : tokens[(s - 1) * BB + b];
        val = embed[tok * EE + (k - ERD)];
    }
    g_xseq[sb * XDIM + k] = val;
}

// ---------------- kernel 1b: x-part gate GEMM --------------------------------
// xg[sb][grow] = sum_k<364 W_ih[grow][k] * x[sb][k]. Tiled like k_logits.
// Output scattered into g_xg[s][grow][b] for coalesced LSTM reads.
#define GM 64
#define GN 128
#define GK 16
#define GKT 23              // ceil(364/16); k >= 364 zero-padded

__device__ __forceinline__ float4 ld4z(const float* p, int k) {
    return (k < XDIM) ? *(const float4*)(p + k) : make_float4(0.f, 0.f, 0.f, 0.f);
}

__global__ __launch_bounds__(256, 2) void k_xgemm(const float* __restrict__ Wih) {
    __shared__ float sA[GK * GM];
    __shared__ float sW[GK * GN];

    const int tid = threadIdx.x;
    const int n0 = blockIdx.x * GN;
    const int m0 = blockIdx.y * GM;
    const int tm = tid >> 4;
    const int tn = tid & 15;

    const int ar = tid >> 2;
    const int ak = (tid & 3) * 4;
    const int wr = tid >> 1;
    const int wk = (tid & 1) * 8;
    const float* gA = g_xseq + (size_t)(m0 + ar) * XDIM;
    const float* gW = Wih + (size_t)(n0 + wr) * XDIM;

    unsigned long long acc[4][4];
    #pragma unroll
    for (int m = 0; m < 4; ++m)
        #pragma unroll
        for (int j = 0; j < 4; ++j) acc[m][j] = 0ull;

    float4 pa  = ld4z(gA, ak);
    float4 pw0 = ld4z(gW, wk);
    float4 pw1 = ld4z(gW, wk + 4);

    for (int t = 0; t < GKT; ++t) {
        sA[(ak + 0) * GM + ar] = pa.x;
        sA[(ak + 1) * GM + ar] = pa.y;
        sA[(ak + 2) * GM + ar] = pa.z;
        sA[(ak + 3) * GM + ar] = pa.w;
        sW[(wk + 0) * GN + wr] = pw0.x;
        sW[(wk + 1) * GN + wr] = pw0.y;
        sW[(wk + 2) * GN + wr] = pw0.z;
        sW[(wk + 3) * GN + wr] = pw0.w;
        sW[(wk + 4) * GN + wr] = pw1.x;
        sW[(wk + 5) * GN + wr] = pw1.y;
        sW[(wk + 6) * GN + wr] = pw1.z;
        sW[(wk + 7) * GN + wr] = pw1.w;
        __syncthreads();
        if (t + 1 < GKT) {
            int kb = (t + 1) * GK;
            pa  = ld4z(gA, kb + ak);
            pw0 = ld4z(gW, kb + wk);
            pw1 = ld4z(gW, kb + wk + 4);
        }
        #pragma unroll
        for (int k = 0; k < GK; ++k) {
            float4 av = *(const float4*)(sA + k * GM + tm * 4);
            const float* wrow = sW + k * GN + tn * 2;
            unsigned long long w0 = *(const unsigned long long*)(wrow);
            unsigned long long w1 = *(const unsigned long long*)(wrow + 32);
            unsigned long long w2 = *(const unsigned long long*)(wrow + 64);
            unsigned long long w3 = *(const unsigned long long*)(wrow + 96);
            unsigned long long am;
            am = dup2(av.x);
            ffma2(acc[0][0], w0, am); ffma2(acc[0][1], w1, am);
            ffma2(acc[0][2], w2, am); ffma2(acc[0][3], w3, am);
            am = dup2(av.y);
            ffma2(acc[1][0], w0, am); ffma2(acc[1][1], w1, am);
            ffma2(acc[1][2], w2, am); ffma2(acc[1][3], w3, am);
            am = dup2(av.z);
            ffma2(acc[2][0], w0, am); ffma2(acc[2][1], w1, am);
            ffma2(acc[2][2], w2, am); ffma2(acc[2][3], w3, am);
            am = dup2(av.w);
            ffma2(acc[3][0], w0, am); ffma2(acc[3][1], w1, am);
            ffma2(acc[3][2], w2, am); ffma2(acc[3][3], w3, am);
        }
        __syncthreads();
    }

    #pragma unroll
    for (int m = 0; m < 4; ++m) {
        int sb = m0 + tm * 4 + m;
        int s = sb >> 3, b = sb & 7;
        float* base = g_xg + (size_t)s * (4 * HH * BB) + b;
        #pragma unroll
        for (int j = 0; j < 4; ++j) {
            float2 f = unpack2(acc[m][j]);
            int row = n0 + tn * 2 + j * 32;
            base[(size_t)row * 8] = f.x;
            base[(size_t)(row + 1) * 8] = f.y;
        }
    }
}

// ---------------- kernel 2: persistent LSTM v5 (h-part only) -----------------
// 64 blocks x 256 threads. Block owns 8 h -> 32 gate rows; thread (r, c)
// handles rows r, r+16 over k_h = 16i+c (32 slices). x-part comes from g_xg.
__global__ __launch_bounds__(256, 1) void k_lstm(
    const float* __restrict__ hiddens,
    const float* __restrict__ W_hh,
    const float* __restrict__ b_ih, const float* __restrict__ b_hh) {
    extern __shared__ float sm[];
    float* h_s    = sm;                        // 4096
    float* gate_s = h_s + HS_FLOATS;           // 256
    float* c_s    = gate_s + 256;              // 64
    float* bias_s = c_s + 64;                  // 32
    double* nl_s  = (double*)(bias_s + 32);    // 256 doubles

    const int tid = threadIdx.x;
    const int r = tid >> 4;
    const int c = tid & 15;
    const int j0 = blockIdx.x * HPB;

    // recurrent weight slices: rows r and r+16, k_h = 16i+c
    float wA[NIH], wB[NIH];
    {
        const int growA = (r >> 3) * HH + j0 + (r & 7);
        const int growB = ((r + 16) >> 3) * HH + j0 + ((r + 16) & 7);
        #pragma unroll
        for (int i = 0; i < NIH; ++i) {
            wA[i] = W_hh[(size_t)growA * HH + 16 * i + c];
            wB[i] = W_hh[(size_t)growB * HH + 16 * i + c];
        }
    }
    if (tid < 32) {
        int g2 = tid >> 3, j2 = tid & 7;
        bias_s[tid] = b_ih[g2 * HH + j0 + j2] + b_hh[g2 * HH + j0 + j2];
    }
    if (tid < 64) {
        int j2 = tid >> 3, b = tid & 7;
        c_s[tid] = hiddens[b * HH + j0 + j2];
    }
    __syncthreads();

    const unsigned long long ONE2 = dup2(1.0f);
    const int grow_l = tid >> 3;          // 0..31 (for xg/gate/bias phase)
    const int b_l = tid & 7;
    const int growG = (grow_l >> 3) * HH + j0 + (grow_l & 7);

    for (int s = 0; s < SQ; ++s) {
        // wait for all blocks to finish step s-1
        if (s > 0) {
            if (tid == 0) {
                unsigned v;
                do {
                    asm volatile("ld.acquire.gpu.global.u32 %0, [%1];"
                                 : "=r"(v) : "l"(&g_bars[s - 1]) : "memory");
                } while (v < (unsigned)LSTM_BLOCKS);
            }
            __syncthreads();
        }
        // stage h_{s-1}
        if (s == 0) {
            #pragma unroll
            for (int it = 0; it < 4; ++it) {
                int idx = tid + it * 256;
                int j = idx & 511, half = idx >> 9;
                float4 v;
                v.x = hiddens[(half * 4 + 0) * HH + j];
                v.y = hiddens[(half * 4 + 1) * HH + j];
                v.z = hiddens[(half * 4 + 2) * HH + j];
                v.w = hiddens[(half * 4 + 3) * HH + j];
                *(float4*)(h_s + (j >> 4) * 128 + half * 64 + (j & 15) * 4) = v;
            }
        } else {
            const float4* src = (const float4*)(g_hs2 + (size_t)(s - 1) * HH * BB);
            #pragma unroll
            for (int it = 0; it < 4; ++it) {
                int idx = tid + it * 256;
                int j = idx >> 1, half = idx & 1;
                float4 v = __ldcg(src + idx);
                *(float4*)(h_s + (j >> 4) * 128 + half * 64 + (j & 15) * 4) = v;
            }
        }
        // prefetch x-part gate value for (grow_l, b_l)
        float xgv = __ldcg(&g_xg[(size_t)s * (4 * HH * BB) + (size_t)growG * 8 + b_l]);
        __syncthreads();

        // h-part gate partials
        unsigned long long a0 = 0, a1 = 0, a2 = 0, a3 = 0;
        unsigned long long a4 = 0, a5 = 0, a6 = 0, a7 = 0;
        const float* base = h_s + c * 4;
        #pragma unroll
        for (int i = 0; i < NIH; ++i) {
            ulonglong2 x01 = *(const ulonglong2*)(base + i * 128);       // b0..3
            ulonglong2 x23 = *(const ulonglong2*)(base + i * 128 + 64);  // b4..7
            unsigned long long wwA = dup2(wA[i]);
            unsigned long long wwB = dup2(wB[i]);
            ffma2(a0, x01.x, wwA); ffma2(a1, x01.y, wwA);
            ffma2(a2, x23.x, wwA); ffma2(a3, x23.y, wwA);
            ffma2(a4, x01.x, wwB); ffma2(a5, x01.y, wwB);
            ffma2(a6, x23.x, wwB); ffma2(a7, x23.y, wwB);
        }
        #pragma unroll
        for (int mask = 1; mask < 16; mask <<= 1) {
            ffma2(a0, __shfl_xor_sync(0xFFFFFFFFu, a0, mask), ONE2);
            ffma2(a1, __shfl_xor_sync(0xFFFFFFFFu, a1, mask), ONE2);
            ffma2(a2, __shfl_xor_sync(0xFFFFFFFFu, a2, mask), ONE2);
            ffma2(a3, __shfl_xor_sync(0xFFFFFFFFu, a3, mask), ONE2);
            ffma2(a4, __shfl_xor_sync(0xFFFFFFFFu, a4, mask), ONE2);
            ffma2(a5, __shfl_xor_sync(0xFFFFFFFFu, a5, mask), ONE2);
            ffma2(a6, __shfl_xor_sync(0xFFFFFFFFu, a6, mask), ONE2);
            ffma2(a7, __shfl_xor_sync(0xFFFFFFFFu, a7, mask), ONE2);
        }
        if (c == 0) {
            unsigned long long* gs = (unsigned long long*)gate_s;
            gs[r * 4 + 0] = a0; gs[r * 4 + 1] = a1;
            gs[r * 4 + 2] = a2; gs[r * 4 + 3] = a3;
            gs[(r + 16) * 4 + 0] = a4; gs[(r + 16) * 4 + 1] = a5;
            gs[(r + 16) * 4 + 2] = a6; gs[(r + 16) * 4 + 3] = a7;
        }
        __syncthreads();

        // cell phase A: one DP nonlinearity per thread (gate = h_part + xg + bias)
        {
            double val = (double)(gate_s[tid] + xgv + bias_s[grow_l]);
            int gg = grow_l >> 3;
            nl_s[tid] = (gg == 2) ? tanh(val) : 1.0 / (1.0 + exp(-val));
        }
        __syncthreads();
        // cell phase B: 64 threads; write h to BOTH layouts
        if (tid < 64) {
            int j2 = tid >> 3, b = tid & 7;
            double si = nl_s[tid];
            double sf = nl_s[64 + tid];
            double tg = nl_s[128 + tid];
            double so = nl_s[192 + tid];
            double cn = sf * (double)c_s[tid] + si * tg;
            float cnf = (float)cn;
            float hnf = (float)(so * tanh((double)cnf));
            c_s[tid] = cnf;
            g_hs[(size_t)(s * 8 + b) * HH + j0 + j2] = hnf;
            g_hs2[(size_t)s * HH * BB + (j0 + j2) * 8 + b] = hnf;
        }
        __syncthreads();

        if (s + 1 < SQ) {
            if (tid == 0)
                asm volatile("red.release.gpu.global.add.u32 [%0], %1;"
                             :: "l"(&g_bars[s]), "r"(1u) : "memory");
        }
    }
}

// ---------------- kernel 3: fp32 f32x2 logits GEMM (R12-exact) ---------------
#define BMX 64
#define BNX 128
#define BKX 16

__global__ __launch_bounds__(256, 2) void k_logits(const float* __restrict__ Wout,
                                                   const float* __restrict__ bout) {
    __shared__ float sA[BKX * BMX];
    __shared__ float sW[BKX * BNX];
    __shared__ unsigned long long sKey[BMX];

    const int tid = threadIdx.x;
    const int n0 = blockIdx.x * BNX;
    const int m0 = blockIdx.y * BMX;
    const int tm = tid >> 4;
    const int tn = tid & 15;

    if (tid < BMX) sKey[tid] = 0ull;

    const int ar = tid >> 2;
    const int ak = (tid & 3) * 4;
    const int wr = tid >> 1;
    const int wk = (tid & 1) * 8;
    const float* gA = g_hs + (size_t)(m0 + ar) * HH + ak;
    const float* gW = Wout + (size_t)(n0 + wr) * HH + wk;

    unsigned long long acc[4][4];
    #pragma unroll
    for (int m = 0; m < 4; ++m)
        #pragma unroll
        for (int j = 0; j < 4; ++j) acc[m][j] = 0ull;

    float4 pa  = *(const float4*)gA;
    float4 pw0 = *(const float4*)gW;
    float4 pw1 = *(const float4*)(gW + 4);

    const int NT = HH / BKX;
    for (int t = 0; t < NT; ++t) {
        sA[(ak + 0) * BMX + ar] = pa.x;
        sA[(ak + 1) * BMX + ar] = pa.y;
        sA[(ak + 2) * BMX + ar] = pa.z;
        sA[(ak + 3) * BMX + ar] = pa.w;
        sW[(wk + 0) * BNX + wr] = pw0.x;
        sW[(wk + 1) * BNX + wr] = pw0.y;
        sW[(wk + 2) * BNX + wr] = pw0.z;
        sW[(wk + 3) * BNX + wr] = pw0.w;
        sW[(wk + 4) * BNX + wr] = pw1.x;
        sW[(wk + 5) * BNX + wr] = pw1.y;
        sW[(wk + 6) * BNX + wr] = pw1.z;
        sW[(wk + 7) * BNX + wr] = pw1.w;
        __syncthreads();
        if (t + 1 < NT) {
            pa  = *(const float4*)(gA + (t + 1) * BKX);
            pw0 = *(const float4*)(gW + (t + 1) * BKX);
            pw1 = *(const float4*)(gW + (t + 1) * BKX + 4);
        }
        #pragma unroll
        for (int k = 0; k < BKX; ++k) {
            float4 av = *(const float4*)(sA + k * BMX + tm * 4);
            const float* wrow = sW + k * BNX + tn * 2;
            unsigned long long w0 = *(const unsigned long long*)(wrow);
            unsigned long long w1 = *(const unsigned long long*)(wrow + 32);
            unsigned long long w2 = *(const unsigned long long*)(wrow + 64);
            unsigned long long w3 = *(const unsigned long long*)(wrow + 96);
            unsigned long long am;
            am = dup2(av.x);
            ffma2(acc[0][0], w0, am); ffma2(acc[0][1], w1, am);
            ffma2(acc[0][2], w2, am); ffma2(acc[0][3], w3, am);
            am = dup2(av.y);
            ffma2(acc[1][0], w0, am); ffma2(acc[1][1], w1, am);
            ffma2(acc[1][2], w2, am); ffma2(acc[1][3], w3, am);
            am = dup2(av.z);
            ffma2(acc[2][0], w0, am); ffma2(acc[2][1], w1, am);
            ffma2(acc[2][2], w2, am); ffma2(acc[2][3], w3, am);
            am = dup2(av.w);
            ffma2(acc[3][0], w0, am); ffma2(acc[3][1], w1, am);
            ffma2(acc[3][2], w2, am); ffma2(acc[3][3], w3, am);
        }
        __syncthreads();
    }

    float bias[4][2];
    #pragma unroll
    for (int j = 0; j < 4; ++j) {
        bias[j][0] = __ldg(&bout[n0 + tn * 2 + j * 32]);
        bias[j][1] = __ldg(&bout[n0 + tn * 2 + j * 32 + 1]);
    }
    #pragma unroll
    for (int m = 0; m < 4; ++m) {
        int m_loc = tm * 4 + m;
        float* lrow = g_logits + (size_t)(m0 + m_loc) * VV + n0;
        unsigned long long best = 0ull;
        #pragma unroll
        for (int j = 0; j < 4; ++j) {
            float2 f = unpack2(acc[m][j]);
            float l0 = f.x + bias[j][0];
            float l1 = f.y + bias[j][1];
            int nn = tn * 2 + j * 32;
            *(float2*)(lrow + nn) = make_float2(l0, l1);
            unsigned long long k0 = make_key(l0, n0 + nn);
            unsigned long long k1 = make_key(l1, n0 + nn + 1);
            if (k0 > best) best = k0;
            if (k1 > best) best = k1;
        }
        atomicMax(&sKey[m_loc], best);
    }
    __syncthreads();
    if (tid < BMX) atomicMax(&g_best[m0 + tid], sKey[tid]);
}

// ---------------- kernel 3b: per-row Z + candidates ----------------
__global__ __launch_bounds__(256) void k_scan() {
    const int row = blockIdx.x;
    const int tid = threadIdx.x;
    __shared__ float sSum[256];
    __shared__ int sCnt;
    if (tid == 0) sCnt = 0;
    __syncthreads();

    const float rowmax = key_to_float(g_best[row]);
    const float th = rowmax - CAND_EPS;
    const float* lrow = g_logits + (size_t)row * VV;

    float acc = 0.0f;
    for (int v = tid; v < VV; v += 256) {
        float l = lrow[v];
        acc += expf(l - rowmax);
        if (l >= th) {
            int idx = atomicAdd(&sCnt, 1);
            if (idx < CAND_MAX) g_candv[row * CAND_MAX + idx] = v;
        }
    }
    sSum[tid] = acc;
    __syncthreads();
    for (int st = 128; st > 0; st >>= 1) {
        if (tid < st) sSum[tid] += sSum[tid + st];
        __syncthreads();
    }
    if (tid == 0) {
        g_Z[row] = sSum[0];
        g_candn[row] = (sCnt < CAND_MAX) ? sCnt : CAND_MAX;
    }
}

// ---------------- kernel 3c: fp64 rescore + quantized-softmax argmax ---------
__global__ __launch_bounds__(256) void k_rescore(const float* __restrict__ Wout,
                                                 const float* __restrict__ bout) {
    const int row = blockIdx.x;
    const int tid = threadIdx.x;
    const int warp = tid >> 5, lane = tid & 31;
    __shared__ double sL[CAND_MAX];

    const int n = g_candn[row];
    const float* hrow = g_hs + (size_t)row * HH;

    for (int ci = warp; ci < n; ci += 8) {
        int v = g_candv[row * CAND_MAX + ci];
        const float* wrow = Wout + (size_t)v * HH;
        double d = 0.0;
        #pragma unroll
        for (int k = lane; k < HH; k += 32)
            d += (double)hrow[k] * (double)wrow[k];
        #pragma unroll
        for (int off = 16; off > 0; off >>= 1)
            d += __shfl_down_sync(0xFFFFFFFFu, d, off);
        if (lane == 0) sL[ci] = d + (double)bout[v];
    }
    __syncthreads();

    if (tid == 0) {
        if (n <= 1) {
            g_vstar[row] = (n == 1) ? g_candv[row * CAND_MAX]
                                    : (int)(0xFFFFFFFFu - (unsigned)(g_best[row] & 0xFFFFFFFFull));
        } else {
            double M = sL[0];
            for (int i = 1; i < n; ++i) if (sL[i] > M) M = sL[i];
            float Z = g_Z[row];
            float bestp = -1.0f;
            int bestv = 0x7FFFFFFF;
            for (int i = 0; i < n; ++i) {
                float e = (float)exp(sL[i] - M);
                float p = __fdiv_rn(e, Z);
                int v = g_candv[row * CAND_MAX + i];
                if (p > bestp || (p == bestp && v < bestv)) { bestp = p; bestv = v; }
            }
            g_vstar[row] = bestv;
        }
    }
}

// ---------------- kernel 4: gather ----------------
__global__ void k_gather(const float* __restrict__ transfer, float* __restrict__ out) {
    int row = blockIdx.x;
    int vstar = g_vstar[row];
    const float* src = transfer + (size_t)vstar * EE;
    float* dst = out + (size_t)row * EE;
    for (int e = threadIdx.x; e < EE; e += blockDim.x) dst[e] = src[e];
}

// ---------------- launch ----------------
extern "C" void kernel_launch(void* const* d_in, const int* in_sizes, int n_in,
                              void* d_out, int out_size) {
    const int*   tokens    = (const int*)d_in[0];
    const int*   relations = (const int*)d_in[1];
    const float* hiddens   = (const float*)d_in[2];
    const float* embed     = (const float*)d_in[3];
    const float* transfer  = (const float*)d_in[4];
    const float* rel_emb   = (const float*)d_in[5];
    const float* W_ih      = (const float*)d_in[6];
    const float* W_hh      = (const float*)d_in[7];
    const float* b_ih      = (const float*)d_in[8];
    const float* b_hh      = (const float*)d_in[9];
    const float* W_out     = (const float*)d_in[10];
    const float* b_out     = (const float*)d_in[11];
    float* out = (float*)d_out;

    k_zero<<<8, 256>>>();
    k_xseq<<<MM, 384>>>(tokens, relations, embed, rel_emb);
    k_xgemm<<<dim3((4 * HH) / GN, MM / GM), 256>>>(W_ih);

    size_t smem = (size_t)(HS_FLOATS + 256 + 64 + 32) * sizeof(float)
                + 256 * sizeof(double);
    cudaFuncSetAttribute(k_lstm, cudaFuncAttributeMaxDynamicSharedMemorySize, (int)smem);
    k_lstm<<<LSTM_BLOCKS, 256, smem>>>(hiddens, W_hh, b_ih, b_hh);

    k_logits<<<dim3(VV / BNX, MM / BMX), 256>>>(W_out, b_out);
    k_scan<<<MM, 256>>>();
    k_rescore<<<MM, 256>>>(W_out, b_out);
    k_gather<<<MM, 128>>>(transfer, out);
}

// round 15
// speedup vs baseline: 1.4584x; 1.2021x over previous
#include <cuda_runtime.h>
#include <cuda_bf16.h>
#include <cstdint>

// ---------------- problem constants ----------------
#define SQ   256
#define BB   8
#define VV   32000
#define EE   300
#define HH   512
#define ERD  64
#define XDIM (EE + ERD)     // 364
#define XH   (XDIM + HH)    // 876
#define MM   (SQ * BB)      // 2048

#define LSTM_BLOCKS 128
#define HPB 4               // h indices per block
#define NIH 32              // h k-slices per thread: k_h = 16*i + c

#define CAND_MAX 64
#define CAND_EPS 5e-4f

// h smem layout: (j>>4)*128 + (b>>2)*64 + (j&15)*4 + (b&3)
#define HS_FLOATS (NIH * 128)        // 4096

// ---------------- scratch ----------------
__device__ float g_xseq[MM * XDIM];            // x in [sb][k] layout
__device__ float g_xg[SQ * 4 * HH * BB];       // x-part gates [s][grow][b]
__device__ float g_hs[MM * HH];                // [s*8+b][H] for logits/rescore
__device__ float g_hs2[SQ * HH * BB];          // [s][j][b] staging layout
__device__ float g_logits[(size_t)MM * VV];
__device__ unsigned long long g_best[MM];
__device__ float g_Z[MM];
__device__ int   g_candv[MM * CAND_MAX];
__device__ int   g_candn[MM];
__device__ int   g_vstar[MM];
__device__ unsigned g_bars[SQ];

// ---------------- helpers ----------------
__device__ __forceinline__ void ffma2(unsigned long long &d, unsigned long long a,
                                      unsigned long long b) {
    asm("fma.rn.f32x2 %0, %1, %2, %0;" : "+l"(d) : "l"(a), "l"(b));
}
__device__ __forceinline__ unsigned long long dup2(float f) {
    unsigned long long d;
    asm("mov.b64 %0, {%1, %1};" : "=l"(d) : "f"(f));
    return d;
}
__device__ __forceinline__ float2 unpack2(unsigned long long a) {
    float2 f;
    asm("mov.b64 {%0, %1}, %2;" : "=f"(f.x), "=f"(f.y) : "l"(a));
    return f;
}
__device__ __forceinline__ unsigned long long make_key(float logit, int v) {
    unsigned u = __float_as_uint(logit);
    u = (u & 0x80000000u) ? ~u : (u | 0x80000000u);
    return ((unsigned long long)u << 32) | (unsigned)(0xFFFFFFFFu - (unsigned)v);
}
__device__ __forceinline__ float key_to_float(unsigned long long key) {
    unsigned u = (unsigned)(key >> 32);
    unsigned fb = (u & 0x80000000u) ? (u ^ 0x80000000u) : ~u;
    return __uint_as_float(fb);
}

// accurate fp32 exp: range-reduced degree-7 Taylor, FMA-only (fast-math-proof)
__device__ __forceinline__ float expf_acc(float x) {
    x = fminf(fmaxf(x, -30.0f), 30.0f);
    const float LOG2E  = 1.4426950408889634f;
    const float LN2_HI = 0.6931471824645996f;
    const float LN2_LO = -1.904654323148236e-09f;
    float n = rintf(x * LOG2E);
    float r = __fmaf_rn(-n, LN2_HI, x);
    r = __fmaf_rn(-n, LN2_LO, r);
    float p = 1.9841270e-04f;              // 1/5040
    p = __fmaf_rn(p, r, 1.3888889e-03f);   // 1/720
    p = __fmaf_rn(p, r, 8.3333333e-03f);   // 1/120
    p = __fmaf_rn(p, r, 4.1666667e-02f);   // 1/24
    p = __fmaf_rn(p, r, 1.6666667e-01f);   // 1/6
    p = __fmaf_rn(p, r, 0.5f);
    p = __fmaf_rn(p, r, 1.0f);
    p = __fmaf_rn(p, r, 1.0f);
    int ni = (int)n;
    float sc = __int_as_float((ni + 127) << 23);
    return p * sc;
}
__device__ __forceinline__ float sigmoid_acc(float x) {
    float e = expf_acc(-x);
    return __fdiv_rn(1.0f, 1.0f + e);
}
__device__ __forceinline__ float tanh_acc(float x) {
    float ax = fabsf(x);
    float res;
    if (ax < 0.25f) {
        float y = x * x;
        float p = 2.1869488e-02f;              // 62/2835
        p = __fmaf_rn(p, y, -5.3968254e-02f);  // -17/315
        p = __fmaf_rn(p, y, 1.3333333e-01f);   // 2/15
        p = __fmaf_rn(p, y, -3.3333333e-01f);  // -1/3
        p = p * y;
        res = __fmaf_rn(p, x, x);
    } else {
        float t = expf_acc(2.0f * fminf(ax, 15.0f));
        float m = __fdiv_rn(2.0f, t + 1.0f);
        float v = 1.0f - m;
        res = (x < 0.0f) ? -v : v;
    }
    return res;
}

// ---------------- kernel 0: zero state ----------------
__global__ void k_zero() {
    int t = blockIdx.x * blockDim.x + threadIdx.x;
    if (t < MM) { g_best[t] = 0ull; g_candn[t] = 0; }
    if (t < SQ) g_bars[t] = 0u;
}

// ---------------- kernel 1: x_seq ----------------
__global__ void k_xseq(const int* __restrict__ tokens, const int* __restrict__ relations,
                       const float* __restrict__ embed, const float* __restrict__ rel_emb) {
    int sb = blockIdx.x;
    int s = sb >> 3, b = sb & 7;
    int k = threadIdx.x;
    if (k >= XDIM) return;
    float val;
    if (k < ERD) {
        int r = relations[s * BB + b];
        val = rel_emb[r * ERD + k];
    } else {
        int tok = (s == 0) ? 0 : tokens[(s - 1) * BB + b];
        val = embed[tok * EE + (k - ERD)];
    }
    g_xseq[sb * XDIM + k] = val;
}

// ---------------- kernel 1b: x-part gate GEMM --------------------------------
#define GM 64
#define GN 128
#define GK 16
#define GKT 23

__device__ __forceinline__ float4 ld4z(const float* p, int k) {
    return (k < XDIM) ? *(const float4*)(p + k) : make_float4(0.f, 0.f, 0.f, 0.f);
}

__global__ __launch_bounds__(256, 2) void k_xgemm(const float* __restrict__ Wih) {
    __shared__ float sA[GK * GM];
    __shared__ float sW[GK * GN];

    const int tid = threadIdx.x;
    const int n0 = blockIdx.x * GN;
    const int m0 = blockIdx.y * GM;
    const int tm = tid >> 4;
    const int tn = tid & 15;

    const int ar = tid >> 2;
    const int ak = (tid & 3) * 4;
    const int wr = tid >> 1;
    const int wk = (tid & 1) * 8;
    const float* gA = g_xseq + (size_t)(m0 + ar) * XDIM;
    const float* gW = Wih + (size_t)(n0 + wr) * XDIM;

    unsigned long long acc[4][4];
    #pragma unroll
    for (int m = 0; m < 4; ++m)
        #pragma unroll
        for (int j = 0; j < 4; ++j) acc[m][j] = 0ull;

    float4 pa  = ld4z(gA, ak);
    float4 pw0 = ld4z(gW, wk);
    float4 pw1 = ld4z(gW, wk + 4);

    for (int t = 0; t < GKT; ++t) {
        sA[(ak + 0) * GM + ar] = pa.x;
        sA[(ak + 1) * GM + ar] = pa.y;
        sA[(ak + 2) * GM + ar] = pa.z;
        sA[(ak + 3) * GM + ar] = pa.w;
        sW[(wk + 0) * GN + wr] = pw0.x;
        sW[(wk + 1) * GN + wr] = pw0.y;
        sW[(wk + 2) * GN + wr] = pw0.z;
        sW[(wk + 3) * GN + wr] = pw0.w;
        sW[(wk + 4) * GN + wr] = pw1.x;
        sW[(wk + 5) * GN + wr] = pw1.y;
        sW[(wk + 6) * GN + wr] = pw1.z;
        sW[(wk + 7) * GN + wr] = pw1.w;
        __syncthreads();
        if (t + 1 < GKT) {
            int kb = (t + 1) * GK;
            pa  = ld4z(gA, kb + ak);
            pw0 = ld4z(gW, kb + wk);
            pw1 = ld4z(gW, kb + wk + 4);
        }
        #pragma unroll
        for (int k = 0; k < GK; ++k) {
            float4 av = *(const float4*)(sA + k * GM + tm * 4);
            const float* wrow = sW + k * GN + tn * 2;
            unsigned long long w0 = *(const unsigned long long*)(wrow);
            unsigned long long w1 = *(const unsigned long long*)(wrow + 32);
            unsigned long long w2 = *(const unsigned long long*)(wrow + 64);
            unsigned long long w3 = *(const unsigned long long*)(wrow + 96);
            unsigned long long am;
            am = dup2(av.x);
            ffma2(acc[0][0], w0, am); ffma2(acc[0][1], w1, am);
            ffma2(acc[0][2], w2, am); ffma2(acc[0][3], w3, am);
            am = dup2(av.y);
            ffma2(acc[1][0], w0, am); ffma2(acc[1][1], w1, am);
            ffma2(acc[1][2], w2, am); ffma2(acc[1][3], w3, am);
            am = dup2(av.z);
            ffma2(acc[2][0], w0, am); ffma2(acc[2][1], w1, am);
            ffma2(acc[2][2], w2, am); ffma2(acc[2][3], w3, am);
            am = dup2(av.w);
            ffma2(acc[3][0], w0, am); ffma2(acc[3][1], w1, am);
            ffma2(acc[3][2], w2, am); ffma2(acc[3][3], w3, am);
        }
        __syncthreads();
    }

    #pragma unroll
    for (int m = 0; m < 4; ++m) {
        int sb = m0 + tm * 4 + m;
        int s = sb >> 3, b = sb & 7;
        float* base = g_xg + (size_t)s * (4 * HH * BB) + b;
        #pragma unroll
        for (int j = 0; j < 4; ++j) {
            float2 f = unpack2(acc[m][j]);
            int row = n0 + tn * 2 + j * 32;
            base[(size_t)row * 8] = f.x;
            base[(size_t)(row + 1) * 8] = f.y;
        }
    }
}

// ---------------- kernel 2: persistent LSTM v6 -------------------------------
// 128 blocks x 256 threads, 4 h/block -> 16 gate rows, one row per thread
// (r=tid>>4) over k_h = 16i+c. Nonlinearities: accurate fp32 (FMA polys).
__global__ __launch_bounds__(256, 1) void k_lstm(
    const float* __restrict__ hiddens,
    const float* __restrict__ W_hh,
    const float* __restrict__ b_ih, const float* __restrict__ b_hh) {
    extern __shared__ float sm[];
    float* h_s    = sm;                        // 4096
    float* gate_s = h_s + HS_FLOATS;           // 128
    float* nl_s   = gate_s + 128;              // 128
    float* c_s    = nl_s + 128;                // 32
    float* bias_s = c_s + 32;                  // 16

    const int tid = threadIdx.x;
    const int r = tid >> 4;          // gate row 0..15
    const int c = tid & 15;
    const int j0 = blockIdx.x * HPB;

    // recurrent weight slice for row r: k_h = 16i+c
    float wreg[NIH];
    {
        const int grow = (r >> 2) * HH + j0 + (r & 3);
        #pragma unroll
        for (int i = 0; i < NIH; ++i)
            wreg[i] = W_hh[(size_t)grow * HH + 16 * i + c];
    }
    if (tid < 16) {
        int g2 = tid >> 2, j2 = tid & 3;
        bias_s[tid] = b_ih[g2 * HH + j0 + j2] + b_hh[g2 * HH + j0 + j2];
    }
    if (tid < 32) {
        int j2 = tid >> 3, b = tid & 7;
        c_s[tid] = hiddens[b * HH + j0 + j2];
    }
    __syncthreads();

    const unsigned long long ONE2 = dup2(1.0f);
    const int grow_l = tid >> 3;          // 0..31 (only <16 used in phase A)
    const int b_l = tid & 7;
    const int growG = (grow_l >> 2) * HH + j0 + (grow_l & 3);

    for (int s = 0; s < SQ; ++s) {
        if (s > 0) {
            if (tid == 0) {
                unsigned v;
                do {
                    asm volatile("ld.acquire.gpu.global.u32 %0, [%1];"
                                 : "=r"(v) : "l"(&g_bars[s - 1]) : "memory");
                } while (v < (unsigned)LSTM_BLOCKS);
            }
            __syncthreads();
        }
        // stage h_{s-1}
        if (s == 0) {
            #pragma unroll
            for (int it = 0; it < 4; ++it) {
                int idx = tid + it * 256;
                int j = idx & 511, half = idx >> 9;
                float4 v;
                v.x = hiddens[(half * 4 + 0) * HH + j];
                v.y = hiddens[(half * 4 + 1) * HH + j];
                v.z = hiddens[(half * 4 + 2) * HH + j];
                v.w = hiddens[(half * 4 + 3) * HH + j];
                *(float4*)(h_s + (j >> 4) * 128 + half * 64 + (j & 15) * 4) = v;
            }
        } else {
            const float4* src = (const float4*)(g_hs2 + (size_t)(s - 1) * HH * BB);
            #pragma unroll
            for (int it = 0; it < 4; ++it) {
                int idx = tid + it * 256;
                int j = idx >> 1, half = idx & 1;
                float4 v = __ldcg(src + idx);
                *(float4*)(h_s + (j >> 4) * 128 + half * 64 + (j & 15) * 4) = v;
            }
        }
        // prefetch x-part gate value (only meaningful for tid < 128)
        float xgv = __ldcg(&g_xg[(size_t)s * (4 * HH * BB) + (size_t)growG * 8 + b_l]);
        __syncthreads();

        // h-part gate partials: one row, 32 slices
        unsigned long long a0 = 0, a1 = 0, a2 = 0, a3 = 0;
        const float* base = h_s + c * 4;
        #pragma unroll
        for (int i = 0; i < NIH; ++i) {
            ulonglong2 x01 = *(const ulonglong2*)(base + i * 128);       // b0..3
            ulonglong2 x23 = *(const ulonglong2*)(base + i * 128 + 64);  // b4..7
            unsigned long long ww = dup2(wreg[i]);
            ffma2(a0, x01.x, ww); ffma2(a1, x01.y, ww);
            ffma2(a2, x23.x, ww); ffma2(a3, x23.y, ww);
        }
        #pragma unroll
        for (int mask = 1; mask < 16; mask <<= 1) {
            ffma2(a0, __shfl_xor_sync(0xFFFFFFFFu, a0, mask), ONE2);
            ffma2(a1, __shfl_xor_sync(0xFFFFFFFFu, a1, mask), ONE2);
            ffma2(a2, __shfl_xor_sync(0xFFFFFFFFu, a2, mask), ONE2);
            ffma2(a3, __shfl_xor_sync(0xFFFFFFFFu, a3, mask), ONE2);
        }
        if (c == 0) {
            unsigned long long* gs = (unsigned long long*)gate_s;
            gs[r * 4 + 0] = a0; gs[r * 4 + 1] = a1;
            gs[r * 4 + 2] = a2; gs[r * 4 + 3] = a3;
        }
        __syncthreads();

        // cell phase A: accurate fp32 nonlinearity (threads 0..127)
        if (tid < 128) {
            float val = gate_s[tid] + xgv + bias_s[grow_l];
            int gg = grow_l >> 2;
            nl_s[tid] = (gg == 2) ? tanh_acc(val) : sigmoid_acc(val);
        }
        __syncthreads();
        // cell phase B: 32 threads; write h to BOTH layouts
        if (tid < 32) {
            int j2 = tid >> 3, b = tid & 7;
            float si = nl_s[tid];
            float sf = nl_s[32 + tid];
            float tg = nl_s[64 + tid];
            float so = nl_s[96 + tid];
            float cn = __fmaf_rn(sf, c_s[tid], si * tg);
            float hn = so * tanh_acc(cn);
            c_s[tid] = cn;
            g_hs[(size_t)(s * 8 + b) * HH + j0 + j2] = hn;
            g_hs2[(size_t)s * HH * BB + (j0 + j2) * 8 + b] = hn;
        }
        __syncthreads();

        if (s + 1 < SQ) {
            if (tid == 0)
                asm volatile("red.release.gpu.global.add.u32 [%0], %1;"
                             :: "l"(&g_bars[s]), "r"(1u) : "memory");
        }
    }
}

// ---------------- kernel 3: fp32 f32x2 logits GEMM (R12-exact) ---------------
#define BMX 64
#define BNX 128
#define BKX 16

__global__ __launch_bounds__(256, 2) void k_logits(const float* __restrict__ Wout,
                                                   const float* __restrict__ bout) {
    __shared__ float sA[BKX * BMX];
    __shared__ float sW[BKX * BNX];
    __shared__ unsigned long long sKey[BMX];

    const int tid = threadIdx.x;
    const int n0 = blockIdx.x * BNX;
    const int m0 = blockIdx.y * BMX;
    const int tm = tid >> 4;
    const int tn = tid & 15;

    if (tid < BMX) sKey[tid] = 0ull;

    const int ar = tid >> 2;
    const int ak = (tid & 3) * 4;
    const int wr = tid >> 1;
    const int wk = (tid & 1) * 8;
    const float* gA = g_hs + (size_t)(m0 + ar) * HH + ak;
    const float* gW = Wout + (size_t)(n0 + wr) * HH + wk;

    unsigned long long acc[4][4];
    #pragma unroll
    for (int m = 0; m < 4; ++m)
        #pragma unroll
        for (int j = 0; j < 4; ++j) acc[m][j] = 0ull;

    float4 pa  = *(const float4*)gA;
    float4 pw0 = *(const float4*)gW;
    float4 pw1 = *(const float4*)(gW + 4);

    const int NT = HH / BKX;
    for (int t = 0; t < NT; ++t) {
        sA[(ak + 0) * BMX + ar] = pa.x;
        sA[(ak + 1) * BMX + ar] = pa.y;
        sA[(ak + 2) * BMX + ar] = pa.z;
        sA[(ak + 3) * BMX + ar] = pa.w;
        sW[(wk + 0) * BNX + wr] = pw0.x;
        sW[(wk + 1) * BNX + wr] = pw0.y;
        sW[(wk + 2) * BNX + wr] = pw0.z;
        sW[(wk + 3) * BNX + wr] = pw0.w;
        sW[(wk + 4) * BNX + wr] = pw1.x;
        sW[(wk + 5) * BNX + wr] = pw1.y;
        sW[(wk + 6) * BNX + wr] = pw1.z;
        sW[(wk + 7) * BNX + wr] = pw1.w;
        __syncthreads();
        if (t + 1 < NT) {
            pa  = *(const float4*)(gA + (t + 1) * BKX);
            pw0 = *(const float4*)(gW + (t + 1) * BKX);
            pw1 = *(const float4*)(gW + (t + 1) * BKX + 4);
        }
        #pragma unroll
        for (int k = 0; k < BKX; ++k) {
            float4 av = *(const float4*)(sA + k * BMX + tm * 4);
            const float* wrow = sW + k * BNX + tn * 2;
            unsigned long long w0 = *(const unsigned long long*)(wrow);
            unsigned long long w1 = *(const unsigned long long*)(wrow + 32);
            unsigned long long w2 = *(const unsigned long long*)(wrow + 64);
            unsigned long long w3 = *(const unsigned long long*)(wrow + 96);
            unsigned long long am;
            am = dup2(av.x);
            ffma2(acc[0][0], w0, am); ffma2(acc[0][1], w1, am);
            ffma2(acc[0][2], w2, am); ffma2(acc[0][3], w3, am);
            am = dup2(av.y);
            ffma2(acc[1][0], w0, am); ffma2(acc[1][1], w1, am);
            ffma2(acc[1][2], w2, am); ffma2(acc[1][3], w3, am);
            am = dup2(av.z);
            ffma2(acc[2][0], w0, am); ffma2(acc[2][1], w1, am);
            ffma2(acc[2][2], w2, am); ffma2(acc[2][3], w3, am);
            am = dup2(av.w);
            ffma2(acc[3][0], w0, am); ffma2(acc[3][1], w1, am);
            ffma2(acc[3][2], w2, am); ffma2(acc[3][3], w3, am);
        }
        __syncthreads();
    }

    float bias[4][2];
    #pragma unroll
    for (int j = 0; j < 4; ++j) {
        bias[j][0] = __ldg(&bout[n0 + tn * 2 + j * 32]);
        bias[j][1] = __ldg(&bout[n0 + tn * 2 + j * 32 + 1]);
    }
    #pragma unroll
    for (int m = 0; m < 4; ++m) {
        int m_loc = tm * 4 + m;
        float* lrow = g_logits + (size_t)(m0 + m_loc) * VV + n0;
        unsigned long long best = 0ull;
        #pragma unroll
        for (int j = 0; j < 4; ++j) {
            float2 f = unpack2(acc[m][j]);
            float l0 = f.x + bias[j][0];
            float l1 = f.y + bias[j][1];
            int nn = tn * 2 + j * 32;
            *(float2*)(lrow + nn) = make_float2(l0, l1);
            unsigned long long k0 = make_key(l0, n0 + nn);
            unsigned long long k1 = make_key(l1, n0 + nn + 1);
            if (k0 > best) best = k0;
            if (k1 > best) best = k1;
        }
        atomicMax(&sKey[m_loc], best);
    }
    __syncthreads();
    if (tid < BMX) atomicMax(&g_best[m0 + tid], sKey[tid]);
}

// ---------------- kernel 3b: per-row Z + candidates ----------------
__global__ __launch_bounds__(256) void k_scan() {
    const int row = blockIdx.x;
    const int tid = threadIdx.x;
    __shared__ float sSum[256];
    __shared__ int sCnt;
    if (tid == 0) sCnt = 0;
    __syncthreads();

    const float rowmax = key_to_float(g_best[row]);
    const float th = rowmax - CAND_EPS;
    const float* lrow = g_logits + (size_t)row * VV;

    float acc = 0.0f;
    for (int v = tid; v < VV; v += 256) {
        float l = lrow[v];
        acc += expf(l - rowmax);
        if (l >= th) {
            int idx = atomicAdd(&sCnt, 1);
            if (idx < CAND_MAX) g_candv[row * CAND_MAX + idx] = v;
        }
    }
    sSum[tid] = acc;
    __syncthreads();
    for (int st = 128; st > 0; st >>= 1) {
        if (tid < st) sSum[tid] += sSum[tid + st];
        __syncthreads();
    }
    if (tid == 0) {
        g_Z[row] = sSum[0];
        g_candn[row] = (sCnt < CAND_MAX) ? sCnt : CAND_MAX;
    }
}

// ---------------- kernel 3c: fp64 rescore + quantized-softmax argmax ---------
__global__ __launch_bounds__(256) void k_rescore(const float* __restrict__ Wout,
                                                 const float* __restrict__ bout) {
    const int row = blockIdx.x;
    const int tid = threadIdx.x;
    const int warp = tid >> 5, lane = tid & 31;
    __shared__ double sL[CAND_MAX];

    const int n = g_candn[row];
    const float* hrow = g_hs + (size_t)row * HH;

    for (int ci = warp; ci < n; ci += 8) {
        int v = g_candv[row * CAND_MAX + ci];
        const float* wrow = Wout + (size_t)v * HH;
        double d = 0.0;
        #pragma unroll
        for (int k = lane; k < HH; k += 32)
            d += (double)hrow[k] * (double)wrow[k];
        #pragma unroll
        for (int off = 16; off > 0; off >>= 1)
            d += __shfl_down_sync(0xFFFFFFFFu, d, off);
        if (lane == 0) sL[ci] = d + (double)bout[v];
    }
    __syncthreads();

    if (tid == 0) {
        if (n <= 1) {
            g_vstar[row] = (n == 1) ? g_candv[row * CAND_MAX]
                                    : (int)(0xFFFFFFFFu - (unsigned)(g_best[row] & 0xFFFFFFFFull));
        } else {
            double M = sL[0];
            for (int i = 1; i < n; ++i) if (sL[i] > M) M = sL[i];
            float Z = g_Z[row];
            float bestp = -1.0f;
            int bestv = 0x7FFFFFFF;
            for (int i = 0; i < n; ++i) {
                float e = (float)exp(sL[i] - M);
                float p = __fdiv_rn(e, Z);
                int v = g_candv[row * CAND_MAX + i];
                if (p > bestp || (p == bestp && v < bestv)) { bestp = p; bestv = v; }
            }
            g_vstar[row] = bestv;
        }
    }
}

// ---------------- kernel 4: gather ----------------
__global__ void k_gather(const float* __restrict__ transfer, float* __restrict__ out) {
    int row = blockIdx.x;
    int vstar = g_vstar[row];
    const float* src = transfer + (size_t)vstar * EE;
    float* dst = out + (size_t)row * EE;
    for (int e = threadIdx.x; e < EE; e += blockDim.x) dst[e] = src[e];
}

// ---------------- launch ----------------
extern "C" void kernel_launch(void* const* d_in, const int* in_sizes, int n_in,
                              void* d_out, int out_size) {
    const int*   tokens    = (const int*)d_in[0];
    const int*   relations = (const int*)d_in[1];
    const float* hiddens   = (const float*)d_in[2];
    const float* embed     = (const float*)d_in[3];
    const float* transfer  = (const float*)d_in[4];
    const float* rel_emb   = (const float*)d_in[5];
    const float* W_ih      = (const float*)d_in[6];
    const float* W_hh      = (const float*)d_in[7];
    const float* b_ih      = (const float*)d_in[8];
    const float* b_hh      = (const float*)d_in[9];
    const float* W_out     = (const float*)d_in[10];
    const float* b_out     = (const float*)d_in[11];
    float* out = (float*)d_out;

    k_zero<<<8, 256>>>();
    k_xseq<<<MM, 384>>>(tokens, relations, embed, rel_emb);
    k_xgemm<<<dim3((4 * HH) / GN, MM / GM), 256>>>(W_ih);

    size_t smem = (size_t)(HS_FLOATS + 128 + 128 + 32 + 16) * sizeof(float);
    cudaFuncSetAttribute(k_lstm, cudaFuncAttributeMaxDynamicSharedMemorySize, (int)smem);
    k_lstm<<<LSTM_BLOCKS, 256, smem>>>(hiddens, W_hh, b_ih, b_hh);

    k_logits<<<dim3(VV / BNX, MM / BMX), 256>>>(W_out, b_out);
    k_scan<<<MM, 256>>>();
    k_rescore<<<MM, 256>>>(W_out, b_out);
    k_gather<<<MM, 128>>>(transfer, out);
}

// round 16
// speedup vs baseline: 1.6572x; 1.1363x over previous
#include <cuda_runtime.h>
#include <cuda_bf16.h>
#include <cstdint>

// ---------------- problem constants ----------------
#define SQ   256
#define BB   8
#define VV   32000
#define EE   300
#define HH   512
#define ERD  64
#define XDIM (EE + ERD)     // 364
#define XH   (XDIM + HH)    // 876
#define MM   (SQ * BB)      // 2048

#define LSTM_BLOCKS 128
#define HPB 4               // h indices per block
#define NIH 32              // h k-slices per thread: k_h = 16*i + c

#define CAND_MAX 64
#define CAND_EPS 5e-4f

// h smem layout: (j>>4)*128 + (b>>2)*64 + (j&15)*4 + (b&3)
#define HS_FLOATS (NIH * 128)        // 4096

// ---------------- scratch ----------------
__device__ float g_xseq[MM * XDIM];            // x in [sb][k] layout
__device__ float g_xg[SQ * 4 * HH * BB];       // x-part gates [s][grow][b]
__device__ float g_hs[MM * HH];                // [s*8+b][H] for logits/rescore
__device__ float g_hs2[SQ * HH * BB];          // [s][j][b] staging layout
__device__ float g_logits[(size_t)MM * VV];
__device__ unsigned long long g_best[MM];
__device__ float g_Z[MM];
__device__ int   g_candv[MM * CAND_MAX];
__device__ int   g_candn[MM];
__device__ int   g_vstar[MM];
__device__ unsigned g_bars[SQ];

// ---------------- helpers ----------------
__device__ __forceinline__ void ffma2(unsigned long long &d, unsigned long long a,
                                      unsigned long long b) {
    asm("fma.rn.f32x2 %0, %1, %2, %0;" : "+l"(d) : "l"(a), "l"(b));
}
__device__ __forceinline__ unsigned long long dup2(float f) {
    unsigned long long d;
    asm("mov.b64 %0, {%1, %1};" : "=l"(d) : "f"(f));
    return d;
}
__device__ __forceinline__ float2 unpack2(unsigned long long a) {
    float2 f;
    asm("mov.b64 {%0, %1}, %2;" : "=f"(f.x), "=f"(f.y) : "l"(a));
    return f;
}
__device__ __forceinline__ unsigned long long make_key(float logit, int v) {
    unsigned u = __float_as_uint(logit);
    u = (u & 0x80000000u) ? ~u : (u | 0x80000000u);
    return ((unsigned long long)u << 32) | (unsigned)(0xFFFFFFFFu - (unsigned)v);
}
__device__ __forceinline__ float key_to_float(unsigned long long key) {
    unsigned u = (unsigned)(key >> 32);
    unsigned fb = (u & 0x80000000u) ? (u ^ 0x80000000u) : ~u;
    return __uint_as_float(fb);
}

// accurate fp32 exp: range-reduced degree-7 Taylor, FMA-only (fast-math-proof)
__device__ __forceinline__ float expf_acc(float x) {
    x = fminf(fmaxf(x, -30.0f), 30.0f);
    const float LOG2E  = 1.4426950408889634f;
    const float LN2_HI = 0.6931471824645996f;
    const float LN2_LO = -1.904654323148236e-09f;
    float n = rintf(x * LOG2E);
    float r = __fmaf_rn(-n, LN2_HI, x);
    r = __fmaf_rn(-n, LN2_LO, r);
    float p = 1.9841270e-04f;
    p = __fmaf_rn(p, r, 1.3888889e-03f);
    p = __fmaf_rn(p, r, 8.3333333e-03f);
    p = __fmaf_rn(p, r, 4.1666667e-02f);
    p = __fmaf_rn(p, r, 1.6666667e-01f);
    p = __fmaf_rn(p, r, 0.5f);
    p = __fmaf_rn(p, r, 1.0f);
    p = __fmaf_rn(p, r, 1.0f);
    int ni = (int)n;
    float sc = __int_as_float((ni + 127) << 23);
    return p * sc;
}
__device__ __forceinline__ float sigmoid_acc(float x) {
    float e = expf_acc(-x);
    return __fdiv_rn(1.0f, 1.0f + e);
}
__device__ __forceinline__ float tanh_acc(float x) {
    float ax = fabsf(x);
    float res;
    if (ax < 0.25f) {
        float y = x * x;
        float p = 2.1869488e-02f;
        p = __fmaf_rn(p, y, -5.3968254e-02f);
        p = __fmaf_rn(p, y, 1.3333333e-01f);
        p = __fmaf_rn(p, y, -3.3333333e-01f);
        p = p * y;
        res = __fmaf_rn(p, x, x);
    } else {
        float t = expf_acc(2.0f * fminf(ax, 15.0f));
        float m = __fdiv_rn(2.0f, t + 1.0f);
        float v = 1.0f - m;
        res = (x < 0.0f) ? -v : v;
    }
    return res;
}

// ---------------- kernel 0: zero state ----------------
__global__ void k_zero() {
    int t = blockIdx.x * blockDim.x + threadIdx.x;
    if (t < MM) { g_best[t] = 0ull; g_candn[t] = 0; }
    if (t < SQ) g_bars[t] = 0u;
}

// ---------------- kernel 1: x_seq ----------------
__global__ void k_xseq(const int* __restrict__ tokens, const int* __restrict__ relations,
                       const float* __restrict__ embed, const float* __restrict__ rel_emb) {
    int sb = blockIdx.x;
    int s = sb >> 3, b = sb & 7;
    int k = threadIdx.x;
    if (k >= XDIM) return;
    float val;
    if (k < ERD) {
        int r = relations[s * BB + b];
        val = rel_emb[r * ERD + k];
    } else {
        int tok = (s == 0) ? 0 : tokens[(s - 1) * BB + b];
        val = embed[tok * EE + (k - ERD)];
    }
    g_xseq[sb * XDIM + k] = val;
}

// ---------------- kernel 1b: x-part gate GEMM --------------------------------
#define GM 64
#define GN 128
#define GK 16
#define GKT 23

__device__ __forceinline__ float4 ld4z(const float* p, int k) {
    return (k < XDIM) ? *(const float4*)(p + k) : make_float4(0.f, 0.f, 0.f, 0.f);
}

__global__ __launch_bounds__(256, 2) void k_xgemm(const float* __restrict__ Wih) {
    __shared__ float sA[GK * GM];
    __shared__ float sW[GK * GN];

    const int tid = threadIdx.x;
    const int n0 = blockIdx.x * GN;
    const int m0 = blockIdx.y * GM;
    const int tm = tid >> 4;
    const int tn = tid & 15;

    const int ar = tid >> 2;
    const int ak = (tid & 3) * 4;
    const int wr = tid >> 1;
    const int wk = (tid & 1) * 8;
    const float* gA = g_xseq + (size_t)(m0 + ar) * XDIM;
    const float* gW = Wih + (size_t)(n0 + wr) * XDIM;

    unsigned long long acc[4][4];
    #pragma unroll
    for (int m = 0; m < 4; ++m)
        #pragma unroll
        for (int j = 0; j < 4; ++j) acc[m][j] = 0ull;

    float4 pa  = ld4z(gA, ak);
    float4 pw0 = ld4z(gW, wk);
    float4 pw1 = ld4z(gW, wk + 4);

    for (int t = 0; t < GKT; ++t) {
        sA[(ak + 0) * GM + ar] = pa.x;
        sA[(ak + 1) * GM + ar] = pa.y;
        sA[(ak + 2) * GM + ar] = pa.z;
        sA[(ak + 3) * GM + ar] = pa.w;
        sW[(wk + 0) * GN + wr] = pw0.x;
        sW[(wk + 1) * GN + wr] = pw0.y;
        sW[(wk + 2) * GN + wr] = pw0.z;
        sW[(wk + 3) * GN + wr] = pw0.w;
        sW[(wk + 4) * GN + wr] = pw1.x;
        sW[(wk + 5) * GN + wr] = pw1.y;
        sW[(wk + 6) * GN + wr] = pw1.z;
        sW[(wk + 7) * GN + wr] = pw1.w;
        __syncthreads();
        if (t + 1 < GKT) {
            int kb = (t + 1) * GK;
            pa  = ld4z(gA, kb + ak);
            pw0 = ld4z(gW, kb + wk);
            pw1 = ld4z(gW, kb + wk + 4);
        }
        #pragma unroll
        for (int k = 0; k < GK; ++k) {
            float4 av = *(const float4*)(sA + k * GM + tm * 4);
            const float* wrow = sW + k * GN + tn * 2;
            unsigned long long w0 = *(const unsigned long long*)(wrow);
            unsigned long long w1 = *(const unsigned long long*)(wrow + 32);
            unsigned long long w2 = *(const unsigned long long*)(wrow + 64);
            unsigned long long w3 = *(const unsigned long long*)(wrow + 96);
            unsigned long long am;
            am = dup2(av.x);
            ffma2(acc[0][0], w0, am); ffma2(acc[0][1], w1, am);
            ffma2(acc[0][2], w2, am); ffma2(acc[0][3], w3, am);
            am = dup2(av.y);
            ffma2(acc[1][0], w0, am); ffma2(acc[1][1], w1, am);
            ffma2(acc[1][2], w2, am); ffma2(acc[1][3], w3, am);
            am = dup2(av.z);
            ffma2(acc[2][0], w0, am); ffma2(acc[2][1], w1, am);
            ffma2(acc[2][2], w2, am); ffma2(acc[2][3], w3, am);
            am = dup2(av.w);
            ffma2(acc[3][0], w0, am); ffma2(acc[3][1], w1, am);
            ffma2(acc[3][2], w2, am); ffma2(acc[3][3], w3, am);
        }
        __syncthreads();
    }

    #pragma unroll
    for (int m = 0; m < 4; ++m) {
        int sb = m0 + tm * 4 + m;
        int s = sb >> 3, b = sb & 7;
        float* base = g_xg + (size_t)s * (4 * HH * BB) + b;
        #pragma unroll
        for (int j = 0; j < 4; ++j) {
            float2 f = unpack2(acc[m][j]);
            int row = n0 + tn * 2 + j * 32;
            base[(size_t)row * 8] = f.x;
            base[(size_t)(row + 1) * 8] = f.y;
        }
    }
}

// ---------------- kernel 2: persistent LSTM v6 (R15-exact) -------------------
__global__ __launch_bounds__(256, 1) void k_lstm(
    const float* __restrict__ hiddens,
    const float* __restrict__ W_hh,
    const float* __restrict__ b_ih, const float* __restrict__ b_hh) {
    extern __shared__ float sm[];
    float* h_s    = sm;                        // 4096
    float* gate_s = h_s + HS_FLOATS;           // 128
    float* nl_s   = gate_s + 128;              // 128
    float* c_s    = nl_s + 128;                // 32
    float* bias_s = c_s + 32;                  // 16

    const int tid = threadIdx.x;
    const int r = tid >> 4;
    const int c = tid & 15;
    const int j0 = blockIdx.x * HPB;

    float wreg[NIH];
    {
        const int grow = (r >> 2) * HH + j0 + (r & 3);
        #pragma unroll
        for (int i = 0; i < NIH; ++i)
            wreg[i] = W_hh[(size_t)grow * HH + 16 * i + c];
    }
    if (tid < 16) {
        int g2 = tid >> 2, j2 = tid & 3;
        bias_s[tid] = b_ih[g2 * HH + j0 + j2] + b_hh[g2 * HH + j0 + j2];
    }
    if (tid < 32) {
        int j2 = tid >> 3, b = tid & 7;
        c_s[tid] = hiddens[b * HH + j0 + j2];
    }
    __syncthreads();

    const unsigned long long ONE2 = dup2(1.0f);
    const int grow_l = tid >> 3;
    const int b_l = tid & 7;
    const int growG = (grow_l >> 2) * HH + j0 + (grow_l & 3);

    for (int s = 0; s < SQ; ++s) {
        if (s > 0) {
            if (tid == 0) {
                unsigned v;
                do {
                    asm volatile("ld.acquire.gpu.global.u32 %0, [%1];"
                                 : "=r"(v) : "l"(&g_bars[s - 1]) : "memory");
                } while (v < (unsigned)LSTM_BLOCKS);
            }
            __syncthreads();
        }
        if (s == 0) {
            #pragma unroll
            for (int it = 0; it < 4; ++it) {
                int idx = tid + it * 256;
                int j = idx & 511, half = idx >> 9;
                float4 v;
                v.x = hiddens[(half * 4 + 0) * HH + j];
                v.y = hiddens[(half * 4 + 1) * HH + j];
                v.z = hiddens[(half * 4 + 2) * HH + j];
                v.w = hiddens[(half * 4 + 3) * HH + j];
                *(float4*)(h_s + (j >> 4) * 128 + half * 64 + (j & 15) * 4) = v;
            }
        } else {
            const float4* src = (const float4*)(g_hs2 + (size_t)(s - 1) * HH * BB);
            #pragma unroll
            for (int it = 0; it < 4; ++it) {
                int idx = tid + it * 256;
                int j = idx >> 1, half = idx & 1;
                float4 v = __ldcg(src + idx);
                *(float4*)(h_s + (j >> 4) * 128 + half * 64 + (j & 15) * 4) = v;
            }
        }
        float xgv = __ldcg(&g_xg[(size_t)s * (4 * HH * BB) + (size_t)growG * 8 + b_l]);
        __syncthreads();

        unsigned long long a0 = 0, a1 = 0, a2 = 0, a3 = 0;
        const float* base = h_s + c * 4;
        #pragma unroll
        for (int i = 0; i < NIH; ++i) {
            ulonglong2 x01 = *(const ulonglong2*)(base + i * 128);
            ulonglong2 x23 = *(const ulonglong2*)(base + i * 128 + 64);
            unsigned long long ww = dup2(wreg[i]);
            ffma2(a0, x01.x, ww); ffma2(a1, x01.y, ww);
            ffma2(a2, x23.x, ww); ffma2(a3, x23.y, ww);
        }
        #pragma unroll
        for (int mask = 1; mask < 16; mask <<= 1) {
            ffma2(a0, __shfl_xor_sync(0xFFFFFFFFu, a0, mask), ONE2);
            ffma2(a1, __shfl_xor_sync(0xFFFFFFFFu, a1, mask), ONE2);
            ffma2(a2, __shfl_xor_sync(0xFFFFFFFFu, a2, mask), ONE2);
            ffma2(a3, __shfl_xor_sync(0xFFFFFFFFu, a3, mask), ONE2);
        }
        if (c == 0) {
            unsigned long long* gs = (unsigned long long*)gate_s;
            gs[r * 4 + 0] = a0; gs[r * 4 + 1] = a1;
            gs[r * 4 + 2] = a2; gs[r * 4 + 3] = a3;
        }
        __syncthreads();

        if (tid < 128) {
            float val = gate_s[tid] + xgv + bias_s[grow_l];
            int gg = grow_l >> 2;
            nl_s[tid] = (gg == 2) ? tanh_acc(val) : sigmoid_acc(val);
        }
        __syncthreads();
        if (tid < 32) {
            int j2 = tid >> 3, b = tid & 7;
            float si = nl_s[tid];
            float sf = nl_s[32 + tid];
            float tg = nl_s[64 + tid];
            float so = nl_s[96 + tid];
            float cn = __fmaf_rn(sf, c_s[tid], si * tg);
            float hn = so * tanh_acc(cn);
            c_s[tid] = cn;
            g_hs[(size_t)(s * 8 + b) * HH + j0 + j2] = hn;
            g_hs2[(size_t)s * HH * BB + (j0 + j2) * 8 + b] = hn;
        }
        __syncthreads();

        if (s + 1 < SQ) {
            if (tid == 0)
                asm volatile("red.release.gpu.global.add.u32 [%0], %1;"
                             :: "l"(&g_bars[s]), "r"(1u) : "memory");
        }
    }
}

// ---------------- kernel 3: fp32 f32x2 logits GEMM v3 ------------------------
// BMX=128 (8m x 4 n-pairs per thread), double-buffered smem (ONE sync/iter).
// Per k: 2 LDS.128 (a) + 4 LDS.64 (w, conflict-free) + 8 dup2 + 32 FFMA2.
// Per-(m,n) accumulation remains sequential k=0..511 in identical operand
// order as R12 -> bit-identical logits.
#define BMX 128
#define BNX 128
#define BKX 16

__global__ __launch_bounds__(256, 1) void k_logits(const float* __restrict__ Wout,
                                                   const float* __restrict__ bout) {
    __shared__ float sA[2][BKX * BMX];               // 2 x 8KB
    __shared__ float sW[2][BKX * BNX];               // 2 x 8KB
    __shared__ unsigned long long sKey[BMX];

    const int tid = threadIdx.x;
    const int n0 = blockIdx.x * BNX;
    const int m0 = blockIdx.y * BMX;
    const int tm = tid >> 4;            // m = tm*8 + 0..7
    const int tn = tid & 15;            // n-pairs at tn*2 + j*32

    if (tid < BMX) sKey[tid] = 0ull;

    // staging: row = tid>>1 (0..127), half = tid&1 -> 8 floats
    const int ar = tid >> 1;
    const int ak = (tid & 1) * 8;
    const float* gA = g_hs + (size_t)(m0 + ar) * HH + ak;
    const float* gW = Wout + (size_t)(n0 + ar) * HH + ak;

    unsigned long long acc[8][4];
    #pragma unroll
    for (int m = 0; m < 8; ++m)
        #pragma unroll
        for (int j = 0; j < 4; ++j) acc[m][j] = 0ull;

    float4 pa0 = *(const float4*)gA;
    float4 pa1 = *(const float4*)(gA + 4);
    float4 pw0 = *(const float4*)gW;
    float4 pw1 = *(const float4*)(gW + 4);

    const int NT = HH / BKX;            // 32
    for (int t = 0; t < NT; ++t) {
        const int buf = t & 1;
        // stage (safe: previous readers of this buffer finished before the
        // sync inside iteration t-1)
        float* a_dst = sA[buf] + ar;
        a_dst[(ak + 0) * BMX] = pa0.x;
        a_dst[(ak + 1) * BMX] = pa0.y;
        a_dst[(ak + 2) * BMX] = pa0.z;
        a_dst[(ak + 3) * BMX] = pa0.w;
        a_dst[(ak + 4) * BMX] = pa1.x;
        a_dst[(ak + 5) * BMX] = pa1.y;
        a_dst[(ak + 6) * BMX] = pa1.z;
        a_dst[(ak + 7) * BMX] = pa1.w;
        float* w_dst = sW[buf] + ar;
        w_dst[(ak + 0) * BNX] = pw0.x;
        w_dst[(ak + 1) * BNX] = pw0.y;
        w_dst[(ak + 2) * BNX] = pw0.z;
        w_dst[(ak + 3) * BNX] = pw0.w;
        w_dst[(ak + 4) * BNX] = pw1.x;
        w_dst[(ak + 5) * BNX] = pw1.y;
        w_dst[(ak + 6) * BNX] = pw1.z;
        w_dst[(ak + 7) * BNX] = pw1.w;
        __syncthreads();
        if (t + 1 < NT) {
            const int kb = (t + 1) * BKX;
            pa0 = *(const float4*)(gA + kb);
            pa1 = *(const float4*)(gA + kb + 4);
            pw0 = *(const float4*)(gW + kb);
            pw1 = *(const float4*)(gW + kb + 4);
        }
        #pragma unroll
        for (int k = 0; k < BKX; ++k) {
            const float* arow = sA[buf] + k * BMX + tm * 8;
            float4 av0 = *(const float4*)(arow);
            float4 av1 = *(const float4*)(arow + 4);
            const float* wrow = sW[buf] + k * BNX + tn * 2;
            unsigned long long w0 = *(const unsigned long long*)(wrow);
            unsigned long long w1 = *(const unsigned long long*)(wrow + 32);
            unsigned long long w2 = *(const unsigned long long*)(wrow + 64);
            unsigned long long w3 = *(const unsigned long long*)(wrow + 96);
            unsigned long long am;
            am = dup2(av0.x);
            ffma2(acc[0][0], w0, am); ffma2(acc[0][1], w1, am);
            ffma2(acc[0][2], w2, am); ffma2(acc[0][3], w3, am);
            am = dup2(av0.y);
            ffma2(acc[1][0], w0, am); ffma2(acc[1][1], w1, am);
            ffma2(acc[1][2], w2, am); ffma2(acc[1][3], w3, am);
            am = dup2(av0.z);
            ffma2(acc[2][0], w0, am); ffma2(acc[2][1], w1, am);
            ffma2(acc[2][2], w2, am); ffma2(acc[2][3], w3, am);
            am = dup2(av0.w);
            ffma2(acc[3][0], w0, am); ffma2(acc[3][1], w1, am);
            ffma2(acc[3][2], w2, am); ffma2(acc[3][3], w3, am);
            am = dup2(av1.x);
            ffma2(acc[4][0], w0, am); ffma2(acc[4][1], w1, am);
            ffma2(acc[4][2], w2, am); ffma2(acc[4][3], w3, am);
            am = dup2(av1.y);
            ffma2(acc[5][0], w0, am); ffma2(acc[5][1], w1, am);
            ffma2(acc[5][2], w2, am); ffma2(acc[5][3], w3, am);
            am = dup2(av1.z);
            ffma2(acc[6][0], w0, am); ffma2(acc[6][1], w1, am);
            ffma2(acc[6][2], w2, am); ffma2(acc[6][3], w3, am);
            am = dup2(av1.w);
            ffma2(acc[7][0], w0, am); ffma2(acc[7][1], w1, am);
            ffma2(acc[7][2], w2, am); ffma2(acc[7][3], w3, am);
        }
    }
    __syncthreads();

    // epilogue: +bias, store fp32 logits, per-row argmax keys
    float bias[4][2];
    #pragma unroll
    for (int j = 0; j < 4; ++j) {
        bias[j][0] = __ldg(&bout[n0 + tn * 2 + j * 32]);
        bias[j][1] = __ldg(&bout[n0 + tn * 2 + j * 32 + 1]);
    }
    #pragma unroll
    for (int m = 0; m < 8; ++m) {
        int m_loc = tm * 8 + m;
        float* lrow = g_logits + (size_t)(m0 + m_loc) * VV + n0;
        unsigned long long best = 0ull;
        #pragma unroll
        for (int j = 0; j < 4; ++j) {
            float2 f = unpack2(acc[m][j]);
            float l0 = f.x + bias[j][0];
            float l1 = f.y + bias[j][1];
            int nn = tn * 2 + j * 32;
            *(float2*)(lrow + nn) = make_float2(l0, l1);
            unsigned long long k0 = make_key(l0, n0 + nn);
            unsigned long long k1 = make_key(l1, n0 + nn + 1);
            if (k0 > best) best = k0;
            if (k1 > best) best = k1;
        }
        atomicMax(&sKey[m_loc], best);
    }
    __syncthreads();
    if (tid < BMX) atomicMax(&g_best[m0 + tid], sKey[tid]);
}

// ---------------- kernel 3b: per-row Z + candidates ----------------
__global__ __launch_bounds__(256) void k_scan() {
    const int row = blockIdx.x;
    const int tid = threadIdx.x;
    __shared__ float sSum[256];
    __shared__ int sCnt;
    if (tid == 0) sCnt = 0;
    __syncthreads();

    const float rowmax = key_to_float(g_best[row]);
    const float th = rowmax - CAND_EPS;
    const float* lrow = g_logits + (size_t)row * VV;

    float acc = 0.0f;
    for (int v = tid; v < VV; v += 256) {
        float l = lrow[v];
        acc += expf(l - rowmax);
        if (l >= th) {
            int idx = atomicAdd(&sCnt, 1);
            if (idx < CAND_MAX) g_candv[row * CAND_MAX + idx] = v;
        }
    }
    sSum[tid] = acc;
    __syncthreads();
    for (int st = 128; st > 0; st >>= 1) {
        if (tid < st) sSum[tid] += sSum[tid + st];
        __syncthreads();
    }
    if (tid == 0) {
        g_Z[row] = sSum[0];
        g_candn[row] = (sCnt < CAND_MAX) ? sCnt : CAND_MAX;
    }
}

// ---------------- kernel 3c: fp64 rescore + quantized-softmax argmax ---------
__global__ __launch_bounds__(256) void k_rescore(const float* __restrict__ Wout,
                                                 const float* __restrict__ bout) {
    const int row = blockIdx.x;
    const int tid = threadIdx.x;
    const int warp = tid >> 5, lane = tid & 31;
    __shared__ double sL[CAND_MAX];

    const int n = g_candn[row];
    const float* hrow = g_hs + (size_t)row * HH;

    for (int ci = warp; ci < n; ci += 8) {
        int v = g_candv[row * CAND_MAX + ci];
        const float* wrow = Wout + (size_t)v * HH;
        double d = 0.0;
        #pragma unroll
        for (int k = lane; k < HH; k += 32)
            d += (double)hrow[k] * (double)wrow[k];
        #pragma unroll
        for (int off = 16; off > 0; off >>= 1)
            d += __shfl_down_sync(0xFFFFFFFFu, d, off);
        if (lane == 0) sL[ci] = d + (double)bout[v];
    }
    __syncthreads();

    if (tid == 0) {
        if (n <= 1) {
            g_vstar[row] = (n == 1) ? g_candv[row * CAND_MAX]
                                    : (int)(0xFFFFFFFFu - (unsigned)(g_best[row] & 0xFFFFFFFFull));
        } else {
            double M = sL[0];
            for (int i = 1; i < n; ++i) if (sL[i] > M) M = sL[i];
            float Z = g_Z[row];
            float bestp = -1.0f;
            int bestv = 0x7FFFFFFF;
            for (int i = 0; i < n; ++i) {
                float e = (float)exp(sL[i] - M);
                float p = __fdiv_rn(e, Z);
                int v = g_candv[row * CAND_MAX + i];
                if (p > bestp || (p == bestp && v < bestv)) { bestp = p; bestv = v; }
            }
            g_vstar[row] = bestv;
        }
    }
}

// ---------------- kernel 4: gather ----------------
__global__ void k_gather(const float* __restrict__ transfer, float* __restrict__ out) {
    int row = blockIdx.x;
    int vstar = g_vstar[row];
    const float* src = transfer + (size_t)vstar * EE;
    float* dst = out + (size_t)row * EE;
    for (int e = threadIdx.x; e < EE; e += blockDim.x) dst[e] = src[e];
}

// ---------------- launch ----------------
extern "C" void kernel_launch(void* const* d_in, const int* in_sizes, int n_in,
                              void* d_out, int out_size) {
    const int*   tokens    = (const int*)d_in[0];
    const int*   relations = (const int*)d_in[1];
    const float* hiddens   = (const float*)d_in[2];
    const float* embed     = (const float*)d_in[3];
    const float* transfer  = (const float*)d_in[4];
    const float* rel_emb   = (const float*)d_in[5];
    const float* W_ih      = (const float*)d_in[6];
    const float* W_hh      = (const float*)d_in[7];
    const float* b_ih      = (const float*)d_in[8];
    const float* b_hh      = (const float*)d_in[9];
    const float* W_out     = (const float*)d_in[10];
    const float* b_out     = (const float*)d_in[11];
    float* out = (float*)d_out;

    k_zero<<<8, 256>>>();
    k_xseq<<<MM, 384>>>(tokens, relations, embed, rel_emb);
    k_xgemm<<<dim3((4 * HH) / GN, MM / GM), 256>>>(W_ih);

    size_t smem = (size_t)(HS_FLOATS + 128 + 128 + 32 + 16) * sizeof(float);
    cudaFuncSetAttribute(k_lstm, cudaFuncAttributeMaxDynamicSharedMemorySize, (int)smem);
    k_lstm<<<LSTM_BLOCKS, 256, smem>>>(hiddens, W_hh, b_ih, b_hh);

    k_logits<<<dim3(VV / BNX, MM / BMX), 256>>>(W_out, b_out);
    k_scan<<<MM, 256>>>();
    k_rescore<<<MM, 256>>>(W_out, b_out);
    k_gather<<<MM, 128>>>(transfer, out);
}

// round 17
// speedup vs baseline: 2.0455x; 1.2343x over previous
#include <cuda_runtime.h>
#include <cuda_bf16.h>
#include <cstdint>

// ---------------- problem constants ----------------
#define SQ   256
#define BB   8
#define VV   32000
#define EE   300
#define HH   512
#define ERD  64
#define XDIM (EE + ERD)     // 364
#define XH   (XDIM + HH)    // 876
#define MM   (SQ * BB)      // 2048

#define LSTM_CTAS 128
#define WORKER_CTAS 296
#define HPB 4               // h indices per lstm block
#define NIH 32              // h k-slices per thread

#define CAND_MAX 64
#define CAND_EPS 5e-4f

#define HS_FLOATS (NIH * 128)        // 4096

// logits tiling
#define BMX 128
#define BNX 128
#define BKX 16
#define MTILES (MM / BMX)            // 16
#define NTILES (VV / BNX)            // 250
#define TOTTILES (MTILES * NTILES)   // 4000
#define STEPS_PER_MT (BMX / BB)      // 16

// dynamic smem (floats): worker needs 2*2048 (sA) + 2*2048 (sW) + 256 (sKey u64)
#define SMEM_FLOATS (4 * BKX * BMX + 256)

// ---------------- scratch ----------------
__device__ float g_xseq[MM * XDIM];
__device__ float g_xg[SQ * 4 * HH * BB];
__device__ float g_hs[MM * HH];
__device__ float g_hs2[SQ * HH * BB];
__device__ float g_logits[(size_t)MM * VV];
__device__ unsigned long long g_best[MM];
__device__ float g_Z[MM];
__device__ int   g_candv[MM * CAND_MAX];
__device__ int   g_candn[MM];
__device__ int   g_vstar[MM];
__device__ unsigned g_bars[SQ];
__device__ unsigned g_tile_ctr;

// ---------------- helpers ----------------
__device__ __forceinline__ void ffma2(unsigned long long &d, unsigned long long a,
                                      unsigned long long b) {
    asm("fma.rn.f32x2 %0, %1, %2, %0;" : "+l"(d) : "l"(a), "l"(b));
}
__device__ __forceinline__ unsigned long long dup2(float f) {
    unsigned long long d;
    asm("mov.b64 %0, {%1, %1};" : "=l"(d) : "f"(f));
    return d;
}
__device__ __forceinline__ float2 unpack2(unsigned long long a) {
    float2 f;
    asm("mov.b64 {%0, %1}, %2;" : "=f"(f.x), "=f"(f.y) : "l"(a));
    return f;
}
__device__ __forceinline__ unsigned long long make_key(float logit, int v) {
    unsigned u = __float_as_uint(logit);
    u = (u & 0x80000000u) ? ~u : (u | 0x80000000u);
    return ((unsigned long long)u << 32) | (unsigned)(0xFFFFFFFFu - (unsigned)v);
}
__device__ __forceinline__ float key_to_float(unsigned long long key) {
    unsigned u = (unsigned)(key >> 32);
    unsigned fb = (u & 0x80000000u) ? (u ^ 0x80000000u) : ~u;
    return __uint_as_float(fb);
}

// accurate fp32 exp/sigmoid/tanh (FMA-only, fast-math-proof) — R15-validated
__device__ __forceinline__ float expf_acc(float x) {
    x = fminf(fmaxf(x, -30.0f), 30.0f);
    const float LOG2E  = 1.4426950408889634f;
    const float LN2_HI = 0.6931471824645996f;
    const float LN2_LO = -1.904654323148236e-09f;
    float n = rintf(x * LOG2E);
    float r = __fmaf_rn(-n, LN2_HI, x);
    r = __fmaf_rn(-n, LN2_LO, r);
    float p = 1.9841270e-04f;
    p = __fmaf_rn(p, r, 1.3888889e-03f);
    p = __fmaf_rn(p, r, 8.3333333e-03f);
    p = __fmaf_rn(p, r, 4.1666667e-02f);
    p = __fmaf_rn(p, r, 1.6666667e-01f);
    p = __fmaf_rn(p, r, 0.5f);
    p = __fmaf_rn(p, r, 1.0f);
    p = __fmaf_rn(p, r, 1.0f);
    int ni = (int)n;
    float sc = __int_as_float((ni + 127) << 23);
    return p * sc;
}
__device__ __forceinline__ float sigmoid_acc(float x) {
    float e = expf_acc(-x);
    return __fdiv_rn(1.0f, 1.0f + e);
}
__device__ __forceinline__ float tanh_acc(float x) {
    float ax = fabsf(x);
    float res;
    if (ax < 0.25f) {
        float y = x * x;
        float p = 2.1869488e-02f;
        p = __fmaf_rn(p, y, -5.3968254e-02f);
        p = __fmaf_rn(p, y, 1.3333333e-01f);
        p = __fmaf_rn(p, y, -3.3333333e-01f);
        p = p * y;
        res = __fmaf_rn(p, x, x);
    } else {
        float t = expf_acc(2.0f * fminf(ax, 15.0f));
        float m = __fdiv_rn(2.0f, t + 1.0f);
        float v = 1.0f - m;
        res = (x < 0.0f) ? -v : v;
    }
    return res;
}

// ---------------- kernel 0: zero state ----------------
__global__ void k_zero() {
    int t = blockIdx.x * blockDim.x + threadIdx.x;
    if (t < MM) { g_best[t] = 0ull; g_candn[t] = 0; }
    if (t < SQ) g_bars[t] = 0u;
    if (t == 0) g_tile_ctr = 0u;
}

// ---------------- kernel 1: x_seq ----------------
__global__ void k_xseq(const int* __restrict__ tokens, const int* __restrict__ relations,
                       const float* __restrict__ embed, const float* __restrict__ rel_emb) {
    int sb = blockIdx.x;
    int s = sb >> 3, b = sb & 7;
    int k = threadIdx.x;
    if (k >= XDIM) return;
    float val;
    if (k < ERD) {
        int r = relations[s * BB + b];
        val = rel_emb[r * ERD + k];
    } else {
        int tok = (s == 0) ? 0 : tokens[(s - 1) * BB + b];
        val = embed[tok * EE + (k - ERD)];
    }
    g_xseq[sb * XDIM + k] = val;
}

// ---------------- kernel 1b: x-part gate GEMM (R14-exact) --------------------
#define GM 64
#define GN 128
#define GK 16
#define GKT 23

__device__ __forceinline__ float4 ld4z(const float* p, int k) {
    return (k < XDIM) ? *(const float4*)(p + k) : make_float4(0.f, 0.f, 0.f, 0.f);
}

__global__ __launch_bounds__(256, 2) void k_xgemm(const float* __restrict__ Wih) {
    __shared__ float sA[GK * GM];
    __shared__ float sW[GK * GN];

    const int tid = threadIdx.x;
    const int n0 = blockIdx.x * GN;
    const int m0 = blockIdx.y * GM;
    const int tm = tid >> 4;
    const int tn = tid & 15;

    const int ar = tid >> 2;
    const int ak = (tid & 3) * 4;
    const int wr = tid >> 1;
    const int wk = (tid & 1) * 8;
    const float* gA = g_xseq + (size_t)(m0 + ar) * XDIM;
    const float* gW = Wih + (size_t)(n0 + wr) * XDIM;

    unsigned long long acc[4][4];
    #pragma unroll
    for (int m = 0; m < 4; ++m)
        #pragma unroll
        for (int j = 0; j < 4; ++j) acc[m][j] = 0ull;

    float4 pa  = ld4z(gA, ak);
    float4 pw0 = ld4z(gW, wk);
    float4 pw1 = ld4z(gW, wk + 4);

    for (int t = 0; t < GKT; ++t) {
        sA[(ak + 0) * GM + ar] = pa.x;
        sA[(ak + 1) * GM + ar] = pa.y;
        sA[(ak + 2) * GM + ar] = pa.z;
        sA[(ak + 3) * GM + ar] = pa.w;
        sW[(wk + 0) * GN + wr] = pw0.x;
        sW[(wk + 1) * GN + wr] = pw0.y;
        sW[(wk + 2) * GN + wr] = pw0.z;
        sW[(wk + 3) * GN + wr] = pw0.w;
        sW[(wk + 4) * GN + wr] = pw1.x;
        sW[(wk + 5) * GN + wr] = pw1.y;
        sW[(wk + 6) * GN + wr] = pw1.z;
        sW[(wk + 7) * GN + wr] = pw1.w;
        __syncthreads();
        if (t + 1 < GKT) {
            int kb = (t + 1) * GK;
            pa  = ld4z(gA, kb + ak);
            pw0 = ld4z(gW, kb + wk);
            pw1 = ld4z(gW, kb + wk + 4);
        }
        #pragma unroll
        for (int k = 0; k < GK; ++k) {
            float4 av = *(const float4*)(sA + k * GM + tm * 4);
            const float* wrow = sW + k * GN + tn * 2;
            unsigned long long w0 = *(const unsigned long long*)(wrow);
            unsigned long long w1 = *(const unsigned long long*)(wrow + 32);
            unsigned long long w2 = *(const unsigned long long*)(wrow + 64);
            unsigned long long w3 = *(const unsigned long long*)(wrow + 96);
            unsigned long long am;
            am = dup2(av.x);
            ffma2(acc[0][0], w0, am); ffma2(acc[0][1], w1, am);
            ffma2(acc[0][2], w2, am); ffma2(acc[0][3], w3, am);
            am = dup2(av.y);
            ffma2(acc[1][0], w0, am); ffma2(acc[1][1], w1, am);
            ffma2(acc[1][2], w2, am); ffma2(acc[1][3], w3, am);
            am = dup2(av.z);
            ffma2(acc[2][0], w0, am); ffma2(acc[2][1], w1, am);
            ffma2(acc[2][2], w2, am); ffma2(acc[2][3], w3, am);
            am = dup2(av.w);
            ffma2(acc[3][0], w0, am); ffma2(acc[3][1], w1, am);
            ffma2(acc[3][2], w2, am); ffma2(acc[3][3], w3, am);
        }
        __syncthreads();
    }

    #pragma unroll
    for (int m = 0; m < 4; ++m) {
        int sb = m0 + tm * 4 + m;
        int s = sb >> 3, b = sb & 7;
        float* base = g_xg + (size_t)s * (4 * HH * BB) + b;
        #pragma unroll
        for (int j = 0; j < 4; ++j) {
            float2 f = unpack2(acc[m][j]);
            int row = n0 + tn * 2 + j * 32;
            base[(size_t)row * 8] = f.x;
            base[(size_t)(row + 1) * 8] = f.y;
        }
    }
}

// ---------------- lstm body (R15-exact math; releases bars for ALL s) --------
__device__ void lstm_body(float* sm,
                          const float* __restrict__ hiddens,
                          const float* __restrict__ W_hh,
                          const float* __restrict__ b_ih,
                          const float* __restrict__ b_hh) {
    float* h_s    = sm;                        // 4096
    float* gate_s = h_s + HS_FLOATS;           // 128
    float* nl_s   = gate_s + 128;              // 128
    float* c_s    = nl_s + 128;                // 32
    float* bias_s = c_s + 32;                  // 16

    const int tid = threadIdx.x;
    const int r = tid >> 4;
    const int c = tid & 15;
    const int j0 = blockIdx.x * HPB;

    float wreg[NIH];
    {
        const int grow = (r >> 2) * HH + j0 + (r & 3);
        #pragma unroll
        for (int i = 0; i < NIH; ++i)
            wreg[i] = W_hh[(size_t)grow * HH + 16 * i + c];
    }
    if (tid < 16) {
        int g2 = tid >> 2, j2 = tid & 3;
        bias_s[tid] = b_ih[g2 * HH + j0 + j2] + b_hh[g2 * HH + j0 + j2];
    }
    if (tid < 32) {
        int j2 = tid >> 3, b = tid & 7;
        c_s[tid] = hiddens[b * HH + j0 + j2];
    }
    __syncthreads();

    const unsigned long long ONE2 = dup2(1.0f);
    const int grow_l = tid >> 3;
    const int b_l = tid & 7;
    const int growG = (grow_l >> 2) * HH + j0 + (grow_l & 3);

    for (int s = 0; s < SQ; ++s) {
        if (s > 0) {
            if (tid == 0) {
                unsigned v;
                do {
                    asm volatile("ld.acquire.gpu.global.u32 %0, [%1];"
                                 : "=r"(v) : "l"(&g_bars[s - 1]) : "memory");
                } while (v < (unsigned)LSTM_CTAS);
            }
            __syncthreads();
        }
        if (s == 0) {
            #pragma unroll
            for (int it = 0; it < 4; ++it) {
                int idx = tid + it * 256;
                int j = idx & 511, half = idx >> 9;
                float4 v;
                v.x = hiddens[(half * 4 + 0) * HH + j];
                v.y = hiddens[(half * 4 + 1) * HH + j];
                v.z = hiddens[(half * 4 + 2) * HH + j];
                v.w = hiddens[(half * 4 + 3) * HH + j];
                *(float4*)(h_s + (j >> 4) * 128 + half * 64 + (j & 15) * 4) = v;
            }
        } else {
            const float4* src = (const float4*)(g_hs2 + (size_t)(s - 1) * HH * BB);
            #pragma unroll
            for (int it = 0; it < 4; ++it) {
                int idx = tid + it * 256;
                int j = idx >> 1, half = idx & 1;
                float4 v = __ldcg(src + idx);
                *(float4*)(h_s + (j >> 4) * 128 + half * 64 + (j & 15) * 4) = v;
            }
        }
        float xgv = __ldcg(&g_xg[(size_t)s * (4 * HH * BB) + (size_t)growG * 8 + b_l]);
        __syncthreads();

        unsigned long long a0 = 0, a1 = 0, a2 = 0, a3 = 0;
        const float* base = h_s + c * 4;
        #pragma unroll
        for (int i = 0; i < NIH; ++i) {
            ulonglong2 x01 = *(const ulonglong2*)(base + i * 128);
            ulonglong2 x23 = *(const ulonglong2*)(base + i * 128 + 64);
            unsigned long long ww = dup2(wreg[i]);
            ffma2(a0, x01.x, ww); ffma2(a1, x01.y, ww);
            ffma2(a2, x23.x, ww); ffma2(a3, x23.y, ww);
        }
        #pragma unroll
        for (int mask = 1; mask < 16; mask <<= 1) {
            ffma2(a0, __shfl_xor_sync(0xFFFFFFFFu, a0, mask), ONE2);
            ffma2(a1, __shfl_xor_sync(0xFFFFFFFFu, a1, mask), ONE2);
            ffma2(a2, __shfl_xor_sync(0xFFFFFFFFu, a2, mask), ONE2);
            ffma2(a3, __shfl_xor_sync(0xFFFFFFFFu, a3, mask), ONE2);
        }
        if (c == 0) {
            unsigned long long* gs = (unsigned long long*)gate_s;
            gs[r * 4 + 0] = a0; gs[r * 4 + 1] = a1;
            gs[r * 4 + 2] = a2; gs[r * 4 + 3] = a3;
        }
        __syncthreads();

        if (tid < 128) {
            float val = gate_s[tid] + xgv + bias_s[grow_l];
            int gg = grow_l >> 2;
            nl_s[tid] = (gg == 2) ? tanh_acc(val) : sigmoid_acc(val);
        }
        __syncthreads();
        if (tid < 32) {
            int j2 = tid >> 3, b = tid & 7;
            float si = nl_s[tid];
            float sf = nl_s[32 + tid];
            float tg = nl_s[64 + tid];
            float so = nl_s[96 + tid];
            float cn = __fmaf_rn(sf, c_s[tid], si * tg);
            float hn = so * tanh_acc(cn);
            c_s[tid] = cn;
            g_hs[(size_t)(s * 8 + b) * HH + j0 + j2] = hn;
            g_hs2[(size_t)s * HH * BB + (j0 + j2) * 8 + b] = hn;
        }
        __syncthreads();

        // release progress for step s (ALL steps — workers need s=255 too)
        if (tid == 0)
            asm volatile("red.release.gpu.global.add.u32 [%0], %1;"
                         :: "l"(&g_bars[s]), "r"(1u) : "memory");
    }
}

// ---------------- logits tile (R16-exact math) -------------------------------
__device__ void logits_tile(float* sm, int m0, int n0,
                            const float* __restrict__ Wout,
                            const float* __restrict__ bout) {
    float* sAb = sm;                                   // 2 x BKX*BMX floats
    float* sWb = sm + 2 * BKX * BMX;                   // 2 x BKX*BNX floats
    unsigned long long* sKey = (unsigned long long*)(sm + 4 * BKX * BMX);

    const int tid = threadIdx.x;
    const int tm = tid >> 4;
    const int tn = tid & 15;

    if (tid < BMX) sKey[tid] = 0ull;

    const int ar = tid >> 1;
    const int ak = (tid & 1) * 8;
    const float* gA = g_hs + (size_t)(m0 + ar) * HH + ak;
    const float* gW = Wout + (size_t)(n0 + ar) * HH + ak;

    unsigned long long acc[8][4];
    #pragma unroll
    for (int m = 0; m < 8; ++m)
        #pragma unroll
        for (int j = 0; j < 4; ++j) acc[m][j] = 0ull;

    float4 pa0 = *(const float4*)gA;
    float4 pa1 = *(const float4*)(gA + 4);
    float4 pw0 = *(const float4*)gW;
    float4 pw1 = *(const float4*)(gW + 4);

    const int NT = HH / BKX;            // 32
    for (int t = 0; t < NT; ++t) {
        const int buf = t & 1;
        float* a_dst = sAb + buf * (BKX * BMX) + ar;
        a_dst[(ak + 0) * BMX] = pa0.x;
        a_dst[(ak + 1) * BMX] = pa0.y;
        a_dst[(ak + 2) * BMX] = pa0.z;
        a_dst[(ak + 3) * BMX] = pa0.w;
        a_dst[(ak + 4) * BMX] = pa1.x;
        a_dst[(ak + 5) * BMX] = pa1.y;
        a_dst[(ak + 6) * BMX] = pa1.z;
        a_dst[(ak + 7) * BMX] = pa1.w;
        float* w_dst = sWb + buf * (BKX * BNX) + ar;
        w_dst[(ak + 0) * BNX] = pw0.x;
        w_dst[(ak + 1) * BNX] = pw0.y;
        w_dst[(ak + 2) * BNX] = pw0.z;
        w_dst[(ak + 3) * BNX] = pw0.w;
        w_dst[(ak + 4) * BNX] = pw1.x;
        w_dst[(ak + 5) * BNX] = pw1.y;
        w_dst[(ak + 6) * BNX] = pw1.z;
        w_dst[(ak + 7) * BNX] = pw1.w;
        __syncthreads();
        if (t + 1 < NT) {
            const int kb = (t + 1) * BKX;
            pa0 = *(const float4*)(gA + kb);
            pa1 = *(const float4*)(gA + kb + 4);
            pw0 = *(const float4*)(gW + kb);
            pw1 = *(const float4*)(gW + kb + 4);
        }
        #pragma unroll
        for (int k = 0; k < BKX; ++k) {
            const float* arow = sAb + buf * (BKX * BMX) + k * BMX + tm * 8;
            float4 av0 = *(const float4*)(arow);
            float4 av1 = *(const float4*)(arow + 4);
            const float* wrow = sWb + buf * (BKX * BNX) + k * BNX + tn * 2;
            unsigned long long w0 = *(const unsigned long long*)(wrow);
            unsigned long long w1 = *(const unsigned long long*)(wrow + 32);
            unsigned long long w2 = *(const unsigned long long*)(wrow + 64);
            unsigned long long w3 = *(const unsigned long long*)(wrow + 96);
            unsigned long long am;
            am = dup2(av0.x);
            ffma2(acc[0][0], w0, am); ffma2(acc[0][1], w1, am);
            ffma2(acc[0][2], w2, am); ffma2(acc[0][3], w3, am);
            am = dup2(av0.y);
            ffma2(acc[1][0], w0, am); ffma2(acc[1][1], w1, am);
            ffma2(acc[1][2], w2, am); ffma2(acc[1][3], w3, am);
            am = dup2(av0.z);
            ffma2(acc[2][0], w0, am); ffma2(acc[2][1], w1, am);
            ffma2(acc[2][2], w2, am); ffma2(acc[2][3], w3, am);
            am = dup2(av0.w);
            ffma2(acc[3][0], w0, am); ffma2(acc[3][1], w1, am);
            ffma2(acc[3][2], w2, am); ffma2(acc[3][3], w3, am);
            am = dup2(av1.x);
            ffma2(acc[4][0], w0, am); ffma2(acc[4][1], w1, am);
            ffma2(acc[4][2], w2, am); ffma2(acc[4][3], w3, am);
            am = dup2(av1.y);
            ffma2(acc[5][0], w0, am); ffma2(acc[5][1], w1, am);
            ffma2(acc[5][2], w2, am); ffma2(acc[5][3], w3, am);
            am = dup2(av1.z);
            ffma2(acc[6][0], w0, am); ffma2(acc[6][1], w1, am);
            ffma2(acc[6][2], w2, am); ffma2(acc[6][3], w3, am);
            am = dup2(av1.w);
            ffma2(acc[7][0], w0, am); ffma2(acc[7][1], w1, am);
            ffma2(acc[7][2], w2, am); ffma2(acc[7][3], w3, am);
        }
    }
    __syncthreads();

    float bias[4][2];
    #pragma unroll
    for (int j = 0; j < 4; ++j) {
        bias[j][0] = __ldg(&bout[n0 + tn * 2 + j * 32]);
        bias[j][1] = __ldg(&bout[n0 + tn * 2 + j * 32 + 1]);
    }
    #pragma unroll
    for (int m = 0; m < 8; ++m) {
        int m_loc = tm * 8 + m;
        float* lrow = g_logits + (size_t)(m0 + m_loc) * VV + n0;
        unsigned long long best = 0ull;
        #pragma unroll
        for (int j = 0; j < 4; ++j) {
            float2 f = unpack2(acc[m][j]);
            float l0 = f.x + bias[j][0];
            float l1 = f.y + bias[j][1];
            int nn = tn * 2 + j * 32;
            *(float2*)(lrow + nn) = make_float2(l0, l1);
            unsigned long long k0 = make_key(l0, n0 + nn);
            unsigned long long k1 = make_key(l1, n0 + nn + 1);
            if (k0 > best) best = k0;
            if (k1 > best) best = k1;
        }
        atomicMax(&sKey[m_loc], best);
    }
    __syncthreads();
    if (tid < BMX) atomicMax(&g_best[m0 + tid], sKey[tid]);
}

// ---------------- fused kernel: lstm blocks + logits workers -----------------
__global__ __launch_bounds__(256, 2) void k_fused(
    const float* __restrict__ hiddens, const float* __restrict__ W_hh,
    const float* __restrict__ b_ih, const float* __restrict__ b_hh,
    const float* __restrict__ Wout, const float* __restrict__ bout) {
    extern __shared__ float sm[];
    __shared__ int sTile;

    if (blockIdx.x < LSTM_CTAS) {
        lstm_body(sm, hiddens, W_hh, b_ih, b_hh);
        return;
    }
    // persistent logits worker
    for (;;) {
        if (threadIdx.x == 0) sTile = (int)atomicAdd(&g_tile_ctr, 1u);
        __syncthreads();
        int t = sTile;
        if (t >= TOTTILES) return;
        int mt = t / NTILES;
        int nt = t - mt * NTILES;
        // wait for lstm to finish the last step this m-chunk needs
        if (threadIdx.x == 0) {
            const int s_need = mt * STEPS_PER_MT + (STEPS_PER_MT - 1);
            unsigned v;
            for (;;) {
                asm volatile("ld.acquire.gpu.global.u32 %0, [%1];"
                             : "=r"(v) : "l"(&g_bars[s_need]) : "memory");
                if (v >= (unsigned)LSTM_CTAS) break;
                __nanosleep(256);
            }
        }
        __syncthreads();
        logits_tile(sm, mt * BMX, nt * BNX, Wout, bout);
        __syncthreads();
    }
}

// ---------------- kernel 3b: per-row Z + candidates ----------------
__global__ __launch_bounds__(256) void k_scan() {
    const int row = blockIdx.x;
    const int tid = threadIdx.x;
    __shared__ float sSum[256];
    __shared__ int sCnt;
    if (tid == 0) sCnt = 0;
    __syncthreads();

    const float rowmax = key_to_float(g_best[row]);
    const float th = rowmax - CAND_EPS;
    const float* lrow = g_logits + (size_t)row * VV;

    float acc = 0.0f;
    for (int v = tid; v < VV; v += 256) {
        float l = lrow[v];
        acc += expf(l - rowmax);
        if (l >= th) {
            int idx = atomicAdd(&sCnt, 1);
            if (idx < CAND_MAX) g_candv[row * CAND_MAX + idx] = v;
        }
    }
    sSum[tid] = acc;
    __syncthreads();
    for (int st = 128; st > 0; st >>= 1) {
        if (tid < st) sSum[tid] += sSum[tid + st];
        __syncthreads();
    }
    if (tid == 0) {
        g_Z[row] = sSum[0];
        g_candn[row] = (sCnt < CAND_MAX) ? sCnt : CAND_MAX;
    }
}

// ---------------- kernel 3c: fp64 rescore + quantized-softmax argmax ---------
__global__ __launch_bounds__(256) void k_rescore(const float* __restrict__ Wout,
                                                 const float* __restrict__ bout) {
    const int row = blockIdx.x;
    const int tid = threadIdx.x;
    const int warp = tid >> 5, lane = tid & 31;
    __shared__ double sL[CAND_MAX];

    const int n = g_candn[row];
    const float* hrow = g_hs + (size_t)row * HH;

    for (int ci = warp; ci < n; ci += 8) {
        int v = g_candv[row * CAND_MAX + ci];
        const float* wrow = Wout + (size_t)v * HH;
        double d = 0.0;
        #pragma unroll
        for (int k = lane; k < HH; k += 32)
            d += (double)hrow[k] * (double)wrow[k];
        #pragma unroll
        for (int off = 16; off > 0; off >>= 1)
            d += __shfl_down_sync(0xFFFFFFFFu, d, off);
        if (lane == 0) sL[ci] = d + (double)bout[v];
    }
    __syncthreads();

    if (tid == 0) {
        if (n <= 1) {
            g_vstar[row] = (n == 1) ? g_candv[row * CAND_MAX]
                                    : (int)(0xFFFFFFFFu - (unsigned)(g_best[row] & 0xFFFFFFFFull));
        } else {
            double M = sL[0];
            for (int i = 1; i < n; ++i) if (sL[i] > M) M = sL[i];
            float Z = g_Z[row];
            float bestp = -1.0f;
            int bestv = 0x7FFFFFFF;
            for (int i = 0; i < n; ++i) {
                float e = (float)exp(sL[i] - M);
                float p = __fdiv_rn(e, Z);
                int v = g_candv[row * CAND_MAX + i];
                if (p > bestp || (p == bestp && v < bestv)) { bestp = p; bestv = v; }
            }
            g_vstar[row] = bestv;
        }
    }
}

// ---------------- kernel 4: gather ----------------
__global__ void k_gather(const float* __restrict__ transfer, float* __restrict__ out) {
    int row = blockIdx.x;
    int vstar = g_vstar[row];
    const float* src = transfer + (size_t)vstar * EE;
    float* dst = out + (size_t)row * EE;
    for (int e = threadIdx.x; e < EE; e += blockDim.x) dst[e] = src[e];
}

// ---------------- launch ----------------
extern "C" void kernel_launch(void* const* d_in, const int* in_sizes, int n_in,
                              void* d_out, int out_size) {
    const int*   tokens    = (const int*)d_in[0];
    const int*   relations = (const int*)d_in[1];
    const float* hiddens   = (const float*)d_in[2];
    const float* embed     = (const float*)d_in[3];
    const float* transfer  = (const float*)d_in[4];
    const float* rel_emb   = (const float*)d_in[5];
    const float* W_ih      = (const float*)d_in[6];
    const float* W_hh      = (const float*)d_in[7];
    const float* b_ih      = (const float*)d_in[8];
    const float* b_hh      = (const float*)d_in[9];
    const float* W_out     = (const float*)d_in[10];
    const float* b_out     = (const float*)d_in[11];
    float* out = (float*)d_out;

    k_zero<<<8, 256>>>();
    k_xseq<<<MM, 384>>>(tokens, relations, embed, rel_emb);
    k_xgemm<<<dim3((4 * HH) / GN, MM / GM), 256>>>(W_ih);

    size_t smem = (size_t)SMEM_FLOATS * sizeof(float);   // ~34 KB
    k_fused<<<LSTM_CTAS + WORKER_CTAS, 256, smem>>>(hiddens, W_hh, b_ih, b_hh,
                                                    W_out, b_out);

    k_scan<<<MM, 256>>>();
    k_rescore<<<MM, 256>>>(W_out, b_out);
    k_gather<<<MM, 128>>>(transfer, out);
}